// round 10
// baseline (speedup 1.0000x reference)
#include <cuda_runtime.h>
#include <cuda_fp16.h>
#include <math.h>
#include <cstdint>
#include <cstddef>

// Problem constants
constexpr int BB = 4;
constexpr int LL = 4096;
constexpr int DD = 1024;
constexpr int MM = BB * LL;           // 16384 rows
constexpr int NC = 64;                // scan chunks
constexpr int CL = LL / NC;           // 64 steps per chunk

// ---------------------------------------------------------------------------
// Static device scratch (no allocations allowed)
// ---------------------------------------------------------------------------
__device__ float g_k[(size_t)MM * DD];
__device__ float g_v[(size_t)MM * DD];
__device__ float g_r[(size_t)MM * DD];

__device__ __half g_xkh[(size_t)MM * DD];
__device__ __half g_xkl[(size_t)MM * DD];
__device__ __half g_xvh[(size_t)MM * DD];
__device__ __half g_xvl[(size_t)MM * DD];
__device__ __half g_xrh[(size_t)MM * DD];
__device__ __half g_xrl[(size_t)MM * DD];
__device__ __half g_rwh[(size_t)MM * DD];
__device__ __half g_rwl[(size_t)MM * DD];

__device__ __half g_wh[4][(size_t)DD * DD];
__device__ __half g_wl[4][(size_t)DD * DD];

__device__ float g_sa[NC * BB * DD];
__device__ float g_sb[NC * BB * DD];
__device__ float g_ain[NC * BB * DD];
__device__ float g_bin[NC * BB * DD];

// ---------------------------------------------------------------------------
// PTX helpers (arch-portable: cp.async / ldmatrix / mma.sync)
// ---------------------------------------------------------------------------
__device__ __forceinline__ uint32_t smem_u32(const void* p) {
    uint32_t a;
    asm("{ .reg .u64 t; cvta.to.shared.u64 t, %1; cvt.u32.u64 %0, t; }"
        : "=r"(a) : "l"(p));
    return a;
}

__device__ __forceinline__ void cp16(uint32_t dst, const void* src) {
    asm volatile("cp.async.cg.shared.global [%0], [%1], 16;"
                 :: "r"(dst), "l"(src) : "memory");
}

__device__ __forceinline__ void cp_commit() {
    asm volatile("cp.async.commit_group;" ::: "memory");
}

template <int N>
__device__ __forceinline__ void cp_wait() {
    asm volatile("cp.async.wait_group %0;" :: "n"(N) : "memory");
}

__device__ __forceinline__ void ldsm4(uint32_t* r, uint32_t addr) {
    asm volatile("ldmatrix.sync.aligned.m8n8.x4.shared.b16 {%0,%1,%2,%3}, [%4];"
                 : "=r"(r[0]), "=r"(r[1]), "=r"(r[2]), "=r"(r[3]) : "r"(addr));
}

__device__ __forceinline__ void mma_f16(float* d, const uint32_t* a, const uint32_t* b) {
    asm volatile(
        "mma.sync.aligned.m16n8k16.row.col.f32.f16.f16.f32 "
        "{%0,%1,%2,%3}, {%4,%5,%6,%7}, {%8,%9}, {%0,%1,%2,%3};"
        : "+f"(d[0]), "+f"(d[1]), "+f"(d[2]), "+f"(d[3])
        : "r"(a[0]), "r"(a[1]), "r"(a[2]), "r"(a[3]), "r"(b[0]), "r"(b[1]));
}

__device__ __forceinline__ void split1(float a, __half& h, __half& l) {
    h = __float2half_rn(a);
    l = __float2half_rn(a - __half2float(h));
}

// SW128 swizzle for [128 x 64] fp16 tile: one 128B line per row, 8 chunks.
// Conflict-free for ldmatrix (8 consecutive rows, fixed chunk col).
__device__ __forceinline__ uint32_t phys64(int r, int c) {
    return (uint32_t)(r * 128 + ((c ^ (r & 7)) * 16));
}

// ---------------------------------------------------------------------------
// fp16 split GEMM via mma.sync:  C[m][n] = sum_k A[m][k]*W[n][k]
//   NPASS=3: C = Ah*Wh + Al*Wh + Ah*Wl   (residual ~2^-22, for k projection)
//   NPASS=2: C = Ah*Wh + Al*Wh           (err ~2.8e-4 RMS, for v/r/o)
// CTA tile 128x128, BK=64, 256 threads (8 warps, 2M x 4N), 3-stage ring.
// 2-pass kernel double-buffers ldmatrix fragments (ks+1 prefetch under MMAs).
// ---------------------------------------------------------------------------
constexpr int TILE64_BYTES = 128 * 64 * 2;         // 16384
constexpr int PIPE = 3;
constexpr int NSTAGE = DD / 64;                    // 16

#define STAGE_BYTES_OF(np)  (((np) + 1) * TILE64_BYTES)
#define GEMM_SMEM_OF(np)    (PIPE * STAGE_BYTES_OF(np))

template <int NPASS, bool SIG>
__global__ void __launch_bounds__(256)
gemm_f16(const __half* __restrict__ Ah, const __half* __restrict__ Al,
         const __half* __restrict__ Wh, const __half* __restrict__ Wl,
         float* __restrict__ C)
{
    constexpr int SBYTES = (NPASS + 1) * TILE64_BYTES;
    constexpr int OFF_AH = 0;
    constexpr int OFF_AL = TILE64_BYTES;
    constexpr int OFF_WH = 2 * TILE64_BYTES;
    constexpr int OFF_WL = 3 * TILE64_BYTES;   // only used when NPASS==3
    constexpr bool DB = (NPASS == 2);          // fragment double-buffering

    extern __shared__ char smem[];
    const uint32_t sb = smem_u32(smem);
    const int tid = threadIdx.x;
    const int wid = tid >> 5;
    const int l   = tid & 31;
    const int wm  = wid & 1;          // 0..1 (M)
    const int wn  = wid >> 1;         // 0..3 (N)
    const int bm  = blockIdx.y * 128;
    const int bn  = blockIdx.x * 128;

    // ---- loader mapping: each thread copies 4 x 16B chunks per tile ----
    const int lr = tid >> 1;                   // 0..127
    const int lc = (tid & 1) * 4;              // chunk 0-3 or 4-7
    const size_t arow = (size_t)(bm + lr) * DD;
    const size_t wrow = (size_t)(bn + lr) * DD;
    uint32_t swo[4];
#pragma unroll
    for (int i = 0; i < 4; i++) swo[i] = phys64(lr, lc + i);

    float acc[4][4][4];
#pragma unroll
    for (int i = 0; i < 4; i++)
#pragma unroll
        for (int j = 0; j < 4; j++)
#pragma unroll
            for (int e = 0; e < 4; e++) acc[i][j][e] = 0.0f;

    auto load_stage = [&](int buf, int kc) {
        const uint32_t base = sb + buf * SBYTES;
        const __half* pa_h = Ah + arow + kc + lc * 8;
        const __half* pa_l = Al + arow + kc + lc * 8;
        const __half* pw_h = Wh + wrow + kc + lc * 8;
#pragma unroll
        for (int i = 0; i < 4; i++) {
            cp16(base + OFF_AH + swo[i], pa_h + i * 8);
            cp16(base + OFF_AL + swo[i], pa_l + i * 8);
            cp16(base + OFF_WH + swo[i], pw_h + i * 8);
        }
        if (NPASS == 3) {
            const __half* pw_l = Wl + wrow + kc + lc * 8;
#pragma unroll
            for (int i = 0; i < 4; i++)
                cp16(base + OFF_WL + swo[i], pw_l + i * 8);
        }
    };

    // ---- ldmatrix lane-address components ----
    const int ra = wm * 64 + (l & 7) + ((l >> 3) & 1) * 8;   // + mt*16
    const int ca = (l >> 4) & 1;                              // + ks*2
    const int rb = wn * 32 + (l & 7) + ((l >> 4) & 1) * 8;   // + nt2*16
    const int cb = (l >> 3) & 1;                              // + ks*2

    // fragment buffers (double-buffered for NPASS==2)
    uint32_t fa[DB ? 2 : 1][16], fl[DB ? 2 : 1][16];
    uint32_t fb[DB ? 2 : 1][8],  fbl[NPASS == 3 ? 1 : 1][8];

    auto load_frag = [&](int fbuf, uint32_t base, int ks) {
#pragma unroll
        for (int mt = 0; mt < 4; mt++) {
            const uint32_t off = phys64(ra + mt * 16, ks * 2 + ca);
            ldsm4(fa[fbuf] + mt * 4, base + OFF_AH + off);
            ldsm4(fl[fbuf] + mt * 4, base + OFF_AL + off);
        }
#pragma unroll
        for (int nt2 = 0; nt2 < 2; nt2++) {
            const uint32_t off = phys64(rb + nt2 * 16, ks * 2 + cb);
            ldsm4(fb[fbuf] + nt2 * 4, base + OFF_WH + off);
            if (NPASS == 3) ldsm4(fbl[0] + nt2 * 4, base + OFF_WL + off);
        }
    };

    auto do_mmas = [&](int fbuf) {
#pragma unroll
        for (int mt = 0; mt < 4; mt++)
#pragma unroll
            for (int nt = 0; nt < 4; nt++)
                mma_f16(acc[mt][nt], fa[fbuf] + mt * 4, fb[fbuf] + nt * 2);
#pragma unroll
        for (int mt = 0; mt < 4; mt++)
#pragma unroll
            for (int nt = 0; nt < 4; nt++)
                mma_f16(acc[mt][nt], fl[fbuf] + mt * 4, fb[fbuf] + nt * 2);
        if (NPASS == 3) {
#pragma unroll
            for (int mt = 0; mt < 4; mt++)
#pragma unroll
                for (int nt = 0; nt < 4; nt++)
                    mma_f16(acc[mt][nt], fa[fbuf] + mt * 4, fbl[0] + nt * 2);
        }
    };

    // ---- preload PIPE-1 stages ----
#pragma unroll
    for (int i = 0; i < PIPE - 1; i++) {
        load_stage(i, i * 64);
        cp_commit();
    }

    int buf = 0;
    for (int s = 0; s < NSTAGE; s++) {
        cp_wait<PIPE - 2>();
        __syncthreads();

        if (s + PIPE - 1 < NSTAGE)
            load_stage((s + PIPE - 1) % PIPE, (s + PIPE - 1) * 64);
        cp_commit();

        const uint32_t base = sb + buf * SBYTES;
        if (DB) {
            load_frag(0, base, 0);
#pragma unroll
            for (int ks = 0; ks < 4; ks++) {
                if (ks < 3) load_frag((ks + 1) & 1, base, ks + 1);
                do_mmas(ks & 1);
            }
        } else {
#pragma unroll
            for (int ks = 0; ks < 4; ks++) {
                load_frag(0, base, ks);
                do_mmas(0);
            }
        }
        buf = (buf + 1 == PIPE) ? 0 : buf + 1;
    }

    // ---- epilogue ----
    const int er = l >> 2;            // 0..7
    const int ec = (l & 3) * 2;       // 0,2,4,6
#pragma unroll
    for (int mt = 0; mt < 4; mt++) {
#pragma unroll
        for (int nt = 0; nt < 4; nt++) {
            const int m0 = bm + wm * 64 + mt * 16 + er;
            const int n0 = bn + wn * 32 + nt * 8 + ec;
            float v0 = acc[mt][nt][0], v1 = acc[mt][nt][1];
            float v2 = acc[mt][nt][2], v3 = acc[mt][nt][3];
            if (SIG) {
                v0 = 1.0f / (1.0f + __expf(-v0));
                v1 = 1.0f / (1.0f + __expf(-v1));
                v2 = 1.0f / (1.0f + __expf(-v2));
                v3 = 1.0f / (1.0f + __expf(-v3));
            }
            *(float2*)(C + (size_t)m0 * DD + n0)       = make_float2(v0, v1);
            *(float2*)(C + (size_t)(m0 + 8) * DD + n0) = make_float2(v2, v3);
        }
    }
}

// ---------------------------------------------------------------------------
// Conversion: token-shift mix + fp16 hi/lo split for the three projections
// ---------------------------------------------------------------------------
__global__ void conv_x(const float* __restrict__ x,
                       const float* __restrict__ mk, const float* __restrict__ mv,
                       const float* __restrict__ mr,
                       __half* __restrict__ kh, __half* __restrict__ kl,
                       __half* __restrict__ vh, __half* __restrict__ vl,
                       __half* __restrict__ rh, __half* __restrict__ rl)
{
    const size_t gid = (size_t)blockIdx.x * blockDim.x + threadIdx.x;
    const size_t idx = gid * 4;
    const int d = (int)(idx % DD);
    const size_t m = idx / DD;
    const int lpos = (int)(m & (LL - 1));

    const float4 xc = *(const float4*)(x + idx);
    float4 xp = make_float4(0.f, 0.f, 0.f, 0.f);
    if (lpos != 0) xp = *(const float4*)(x + idx - DD);

    const float xcv[4] = {xc.x, xc.y, xc.z, xc.w};
    const float xpv[4] = {xp.x, xp.y, xp.z, xp.w};

    const float* mixes[3] = {mk, mv, mr};
    __half* outh[3] = {kh, vh, rh};
    __half* outl[3] = {kl, vl, rl};

#pragma unroll
    for (int s = 0; s < 3; s++) {
        const float4 mx = *(const float4*)(mixes[s] + d);
        const float mxv[4] = {mx.x, mx.y, mx.z, mx.w};
        unsigned short hh[4], ll2[4];
#pragma unroll
        for (int j = 0; j < 4; j++) {
            const float a = xcv[j] * mxv[j] + xpv[j] * (1.0f - mxv[j]);
            __half h, lo;
            split1(a, h, lo);
            hh[j] = __half_as_ushort(h);
            ll2[j] = __half_as_ushort(lo);
        }
        *(ushort4*)(outh[s] + idx) = make_ushort4(hh[0], hh[1], hh[2], hh[3]);
        *(ushort4*)(outl[s] + idx) = make_ushort4(ll2[0], ll2[1], ll2[2], ll2[3]);
    }
}

// All 4 weight matrices in one kernel (fp16 hi/lo)
__global__ void conv_w_all(const float* __restrict__ W0, const float* __restrict__ W1,
                           const float* __restrict__ W2, const float* __restrict__ W3,
                           __half* __restrict__ WH, __half* __restrict__ WL)
{
    constexpr size_t WS = (size_t)DD * DD;
    const size_t gid = (size_t)blockIdx.x * blockDim.x + threadIdx.x;
    const size_t idx = gid * 4;                 // over 4*WS elements
    const int mat = (int)(idx / WS);
    const size_t off = idx % WS;
    const float* W = (mat == 0) ? W0 : (mat == 1) ? W1 : (mat == 2) ? W2 : W3;

    const float4 w4 = *(const float4*)(W + off);
    const float wv[4] = {w4.x, w4.y, w4.z, w4.w};
    unsigned short hh[4], ll2[4];
#pragma unroll
    for (int j = 0; j < 4; j++) {
        __half h, lo;
        split1(wv[j], h, lo);
        hh[j] = __half_as_ushort(h);
        ll2[j] = __half_as_ushort(lo);
    }
    *(ushort4*)(WH + idx) = make_ushort4(hh[0], hh[1], hh[2], hh[3]);
    *(ushort4*)(WL + idx) = make_ushort4(ll2[0], ll2[1], ll2[2], ll2[3]);
}

// ---------------------------------------------------------------------------
// WKV scan (chunk-parallel affine recurrence), NC=64 chunks
// ---------------------------------------------------------------------------
__global__ void wkv_phase1(const float* __restrict__ K_,
                           const float* __restrict__ V_,
                           const float* __restrict__ td,
                           float* __restrict__ SA,
                           float* __restrict__ SB)
{
    const int gid = blockIdx.x * blockDim.x + threadIdx.x;
    const int d = gid % DD;
    const int b = (gid / DD) % BB;
    const int c = gid / (DD * BB);

    const float w = -expf(td[d]);
    const float decay = expf(w);

    size_t base = ((size_t)(b * LL + c * CL)) * DD + d;
    float sa = 0.0f, sb = 0.0f;
#pragma unroll 4
    for (int t = 0; t < CL; t++) {
        const float kt = K_[base];
        const float vt = V_[base];
        const float ek = expf(kt);
        sa = decay * sa + ek * vt;
        sb = decay * sb + ek;
        base += DD;
    }
    SA[gid] = sa;
    SB[gid] = sb;
}

__global__ void wkv_phase2(const float* __restrict__ SA,
                           const float* __restrict__ SB,
                           const float* __restrict__ td,
                           float* __restrict__ AIN,
                           float* __restrict__ BIN)
{
    const int gid = blockIdx.x * blockDim.x + threadIdx.x;
    const int d = gid % DD;
    const int b = gid / DD;

    const float w = -expf(td[d]);
    const float dpow = expf(w * (float)CL);

    float a = 0.0f, bs = 0.0f;
#pragma unroll
    for (int c = 0; c < NC; c++) {
        const size_t sidx = ((size_t)c * BB + b) * DD + d;
        AIN[sidx] = a;
        BIN[sidx] = bs;
        a  = dpow * a  + SA[sidx];
        bs = dpow * bs + SB[sidx];
    }
}

__global__ void wkv_phase3(const float* __restrict__ K_,
                           const float* __restrict__ V_,
                           const float* __restrict__ td,
                           const float* __restrict__ tf,
                           const float* __restrict__ AIN,
                           const float* __restrict__ BIN,
                           const float* __restrict__ R,
                           __half* __restrict__ RWH,
                           __half* __restrict__ RWL)
{
    const int gid = blockIdx.x * blockDim.x + threadIdx.x;
    const int d = gid % DD;
    const int b = (gid / DD) % BB;
    const int c = gid / (DD * BB);

    const float w = -expf(td[d]);
    const float decay = expf(w);
    const float u = tf[d];

    float a  = AIN[gid];
    float bs = BIN[gid];

    size_t base = ((size_t)(b * LL + c * CL)) * DD + d;
#pragma unroll 4
    for (int t = 0; t < CL; t++) {
        const float kt = K_[base];
        const float vt = V_[base];
        const float eku = expf(u + kt);
        const float wkv = (a + eku * vt) / fmaxf(bs + eku, 1e-6f);
        const float ek = expf(kt);
        const float rw = R[base] * wkv;
        __half h, lo;
        split1(rw, h, lo);
        RWH[base] = h;
        RWL[base] = lo;
        a  = decay * a  + ek * vt;
        bs = decay * bs + ek;
        base += DD;
    }
}

// ---------------------------------------------------------------------------
extern "C" void kernel_launch(void* const* d_in, const int* in_sizes, int n_in,
                              void* d_out, int out_size)
{
    const float* x  = (const float*)d_in[0];
    const float* td = (const float*)d_in[1];
    const float* tf = (const float*)d_in[2];
    const float* mk = (const float*)d_in[3];
    const float* mv = (const float*)d_in[4];
    const float* mr = (const float*)d_in[5];
    const float* Wk = (const float*)d_in[6];
    const float* Wv = (const float*)d_in[7];
    const float* Wr = (const float*)d_in[8];
    const float* Wo = (const float*)d_in[9];
    float* out = (float*)d_out;

    float *gk, *gv, *gr, *gsa, *gsb, *gain, *gbin;
    __half *xkh, *xkl, *xvh, *xvl, *xrh, *xrl, *rwh, *rwl, *wh, *wl;
    cudaGetSymbolAddress((void**)&gk,   g_k);
    cudaGetSymbolAddress((void**)&gv,   g_v);
    cudaGetSymbolAddress((void**)&gr,   g_r);
    cudaGetSymbolAddress((void**)&gsa,  g_sa);
    cudaGetSymbolAddress((void**)&gsb,  g_sb);
    cudaGetSymbolAddress((void**)&gain, g_ain);
    cudaGetSymbolAddress((void**)&gbin, g_bin);
    cudaGetSymbolAddress((void**)&xkh,  g_xkh);
    cudaGetSymbolAddress((void**)&xkl,  g_xkl);
    cudaGetSymbolAddress((void**)&xvh,  g_xvh);
    cudaGetSymbolAddress((void**)&xvl,  g_xvl);
    cudaGetSymbolAddress((void**)&xrh,  g_xrh);
    cudaGetSymbolAddress((void**)&xrl,  g_xrl);
    cudaGetSymbolAddress((void**)&rwh,  g_rwh);
    cudaGetSymbolAddress((void**)&rwl,  g_rwl);
    cudaGetSymbolAddress((void**)&wh,   g_wh);
    cudaGetSymbolAddress((void**)&wl,   g_wl);

    cudaFuncSetAttribute(gemm_f16<3, false>,
                         cudaFuncAttributeMaxDynamicSharedMemorySize, GEMM_SMEM_OF(3));
    cudaFuncSetAttribute(gemm_f16<2, false>,
                         cudaFuncAttributeMaxDynamicSharedMemorySize, GEMM_SMEM_OF(2));
    cudaFuncSetAttribute(gemm_f16<2, true>,
                         cudaFuncAttributeMaxDynamicSharedMemorySize, GEMM_SMEM_OF(2));

    const size_t WSTRIDE = (size_t)DD * DD;
    const dim3 gg(DD / 128, MM / 128);

    // launch 0: conv_x, 1: conv_w_all
    conv_x<<<(int)(((size_t)MM * DD / 4) / 256), 256>>>(x, mk, mv, mr,
                                                        xkh, xkl, xvh, xvl, xrh, xrl);
    conv_w_all<<<(int)((4 * WSTRIDE / 4) / 256), 256>>>(Wk, Wv, Wr, Wo, wh, wl);

    // launch 2: k (3-pass, feeds exp), 3: v (2-pass, profiled slot), 4: r (2-pass)
    gemm_f16<3, false><<<gg, 256, GEMM_SMEM_OF(3)>>>(xkh, xkl, wh + 0 * WSTRIDE, wl + 0 * WSTRIDE, gk);
    gemm_f16<2, false><<<gg, 256, GEMM_SMEM_OF(2)>>>(xvh, xvl, wh + 1 * WSTRIDE, nullptr, gv);
    gemm_f16<2, true ><<<gg, 256, GEMM_SMEM_OF(2)>>>(xrh, xrl, wh + 2 * WSTRIDE, nullptr, gr);

    // launches 5-7: wkv scan
    wkv_phase1<<<(NC * BB * DD) / 256, 256>>>(gk, gv, td, gsa, gsb);
    wkv_phase2<<<(BB * DD) / 256, 256>>>(gsa, gsb, td, gain, gbin);
    wkv_phase3<<<(NC * BB * DD) / 256, 256>>>(gk, gv, td, tf, gain, gbin, gr, rwh, rwl);

    // launch 8: output projection (2-pass)
    gemm_f16<2, false><<<gg, 256, GEMM_SMEM_OF(2)>>>(rwh, rwl, wh + 3 * WSTRIDE, nullptr, out);
}

// round 11
// speedup vs baseline: 1.2010x; 1.2010x over previous
#include <cuda_runtime.h>
#include <cuda_fp16.h>
#include <math.h>
#include <cstdint>
#include <cstddef>

// Problem constants
constexpr int BB = 4;
constexpr int LL = 4096;
constexpr int DD = 1024;
constexpr int MM = BB * LL;           // 16384 rows
constexpr int NC = 64;                // scan chunks
constexpr int CL = LL / NC;           // 64 steps per chunk

// ---------------------------------------------------------------------------
// Static device scratch (no allocations allowed)
// ---------------------------------------------------------------------------
__device__ float g_k[(size_t)MM * DD];
__device__ float g_v[(size_t)MM * DD];
__device__ float g_r[(size_t)MM * DD];

__device__ __half g_xkh[(size_t)MM * DD];
__device__ __half g_xkl[(size_t)MM * DD];
__device__ __half g_xvh[(size_t)MM * DD];
__device__ __half g_xvl[(size_t)MM * DD];
__device__ __half g_xrh[(size_t)MM * DD];
__device__ __half g_xrl[(size_t)MM * DD];
__device__ __half g_rwh[(size_t)MM * DD];
__device__ __half g_rwl[(size_t)MM * DD];

__device__ __half g_wh[4][(size_t)DD * DD];
__device__ __half g_wl[4][(size_t)DD * DD];

__device__ float g_sa[NC * BB * DD];
__device__ float g_sb[NC * BB * DD];
__device__ float g_ain[NC * BB * DD];
__device__ float g_bin[NC * BB * DD];

// ---------------------------------------------------------------------------
// PTX helpers (arch-portable: cp.async / ldmatrix / mma.sync)
// ---------------------------------------------------------------------------
__device__ __forceinline__ uint32_t smem_u32(const void* p) {
    uint32_t a;
    asm("{ .reg .u64 t; cvta.to.shared.u64 t, %1; cvt.u32.u64 %0, t; }"
        : "=r"(a) : "l"(p));
    return a;
}

__device__ __forceinline__ void cp16(uint32_t dst, const void* src) {
    asm volatile("cp.async.cg.shared.global [%0], [%1], 16;"
                 :: "r"(dst), "l"(src) : "memory");
}

__device__ __forceinline__ void cp_commit() {
    asm volatile("cp.async.commit_group;" ::: "memory");
}

template <int N>
__device__ __forceinline__ void cp_wait() {
    asm volatile("cp.async.wait_group %0;" :: "n"(N) : "memory");
}

__device__ __forceinline__ void ldsm4(uint32_t* r, uint32_t addr) {
    asm volatile("ldmatrix.sync.aligned.m8n8.x4.shared.b16 {%0,%1,%2,%3}, [%4];"
                 : "=r"(r[0]), "=r"(r[1]), "=r"(r[2]), "=r"(r[3]) : "r"(addr));
}

__device__ __forceinline__ void mma_f16(float* d, const uint32_t* a, const uint32_t* b) {
    asm volatile(
        "mma.sync.aligned.m16n8k16.row.col.f32.f16.f16.f32 "
        "{%0,%1,%2,%3}, {%4,%5,%6,%7}, {%8,%9}, {%0,%1,%2,%3};"
        : "+f"(d[0]), "+f"(d[1]), "+f"(d[2]), "+f"(d[3])
        : "r"(a[0]), "r"(a[1]), "r"(a[2]), "r"(a[3]), "r"(b[0]), "r"(b[1]));
}

__device__ __forceinline__ void split1(float a, __half& h, __half& l) {
    h = __float2half_rn(a);
    l = __float2half_rn(a - __half2float(h));
}

// Swizzled smem offset for a [128 x 32] fp16 tile (rows of 4 x 16B chunks).
// 128B lines hold two rows; 8 chunk-positions per line XORed with line&7.
// Conflict-free for ldmatrix (8 consecutive rows, fixed chunk col).
__device__ __forceinline__ uint32_t phys(int r, int c) {
    return (uint32_t)((r >> 1) * 128 + ((((r & 1) * 4 + c) ^ ((r >> 1) & 7)) * 16));
}

// ---------------------------------------------------------------------------
// fp16 split GEMM body via mma.sync:  C[m][n] = sum_k A[m][k]*W[n][k]
//   NPASS=3 (PIPE=3): C = Ah*Wh + Al*Wh + Ah*Wl  (stage 32KB; Wl via fb reload)
//   NPASS=2 (PIPE=4): C = Ah*Wh + Al*Wh          (stage 24KB)
// Both: 96KB smem ring -> 2 CTA/SM. CTA tile 128x128, BK=32, 256 threads.
// Pass-major MMA order: same-acc RAW distance = 16 MMAs.
// ---------------------------------------------------------------------------
constexpr int TILE_BYTES = 128 * 32 * 2;           // 8192
constexpr int NSTAGE = DD / 32;                    // 32
constexpr int GEMM_SMEM = 98304;                   // = 4*24KB = 3*32KB

template <int NPASS, int PIPEN, bool SIG>
__device__ __forceinline__ void gemm_body(
    const __half* __restrict__ Ah, const __half* __restrict__ Al,
    const __half* __restrict__ Wh, const __half* __restrict__ Wl,
    float* __restrict__ C, char* smem)
{
    constexpr int SBYTES = (NPASS + 1) * TILE_BYTES;
    constexpr int OFF_AH = 0;
    constexpr int OFF_AL = TILE_BYTES;
    constexpr int OFF_WH = 2 * TILE_BYTES;
    constexpr int OFF_WL = 3 * TILE_BYTES;   // only when NPASS==3

    const uint32_t sb = smem_u32(smem);
    const int tid = threadIdx.x;
    const int wid = tid >> 5;
    const int l   = tid & 31;
    const int wm  = wid & 1;          // 0..1 (M)
    const int wn  = wid >> 1;         // 0..3 (N)
    const int bm  = blockIdx.y * 128;
    const int bn  = blockIdx.x * 128;

    // ---- loader mapping: each thread copies 2 x 16B chunks per tile ----
    const int lr = tid >> 1;                   // 0..127
    const int lc0 = (tid & 1) * 2;             // chunk 0 or 2
    const size_t arow = (size_t)(bm + lr) * DD;
    const size_t wrow = (size_t)(bn + lr) * DD;
    const uint32_t sw0 = phys(lr, lc0);
    const uint32_t sw1 = phys(lr, lc0 + 1);

    float acc[4][4][4];
#pragma unroll
    for (int i = 0; i < 4; i++)
#pragma unroll
        for (int j = 0; j < 4; j++)
#pragma unroll
            for (int e = 0; e < 4; e++) acc[i][j][e] = 0.0f;

    auto load_stage = [&](int buf, int kc) {
        const uint32_t base = sb + buf * SBYTES;
        const __half* pa_h = Ah + arow + kc + lc0 * 8;
        const __half* pa_l = Al + arow + kc + lc0 * 8;
        const __half* pw_h = Wh + wrow + kc + lc0 * 8;
        cp16(base + OFF_AH + sw0, pa_h);
        cp16(base + OFF_AH + sw1, pa_h + 8);
        cp16(base + OFF_AL + sw0, pa_l);
        cp16(base + OFF_AL + sw1, pa_l + 8);
        cp16(base + OFF_WH + sw0, pw_h);
        cp16(base + OFF_WH + sw1, pw_h + 8);
        if (NPASS == 3) {
            const __half* pw_l = Wl + wrow + kc + lc0 * 8;
            cp16(base + OFF_WL + sw0, pw_l);
            cp16(base + OFF_WL + sw1, pw_l + 8);
        }
    };

    // ---- ldmatrix lane-address components ----
    const int ra = wm * 64 + (l & 7) + ((l >> 3) & 1) * 8;   // + mt*16
    const int ca = (l >> 4) & 1;                              // + ks*2
    const int rb = wn * 32 + (l & 7) + ((l >> 4) & 1) * 8;   // + nt2*16
    const int cb = (l >> 3) & 1;                              // + ks*2

    // ---- preload PIPEN-1 stages ----
#pragma unroll
    for (int i = 0; i < PIPEN - 1; i++) {
        load_stage(i, i * 32);
        cp_commit();
    }

    int buf = 0;
    for (int s = 0; s < NSTAGE; s++) {
        cp_wait<PIPEN - 2>();
        __syncthreads();

        if (s + PIPEN - 1 < NSTAGE)
            load_stage((s + PIPEN - 1) % PIPEN, (s + PIPEN - 1) * 32);
        cp_commit();

        const uint32_t base = sb + buf * SBYTES;
#pragma unroll
        for (int ks = 0; ks < 2; ks++) {
            uint32_t fa[16], fl[16], fb[8];
#pragma unroll
            for (int mt = 0; mt < 4; mt++) {
                const uint32_t off = phys(ra + mt * 16, ks * 2 + ca);
                ldsm4(fa + mt * 4, base + OFF_AH + off);
                ldsm4(fl + mt * 4, base + OFF_AL + off);
            }
            uint32_t offb[2];
#pragma unroll
            for (int nt2 = 0; nt2 < 2; nt2++) {
                offb[nt2] = phys(rb + nt2 * 16, ks * 2 + cb);
                ldsm4(fb + nt2 * 4, base + OFF_WH + offb[nt2]);
            }
            // pass-major: same-acc MMAs are 16 apart (no RAW back-pressure)
#pragma unroll
            for (int mt = 0; mt < 4; mt++)
#pragma unroll
                for (int nt = 0; nt < 4; nt++)
                    mma_f16(acc[mt][nt], fa + mt * 4, fb + nt * 2);
#pragma unroll
            for (int mt = 0; mt < 4; mt++)
#pragma unroll
                for (int nt = 0; nt < 4; nt++)
                    mma_f16(acc[mt][nt], fl + mt * 4, fb + nt * 2);
            if (NPASS == 3) {
                // reload fb with Wl fragments (no extra registers)
#pragma unroll
                for (int nt2 = 0; nt2 < 2; nt2++)
                    ldsm4(fb + nt2 * 4, base + OFF_WL + offb[nt2]);
#pragma unroll
                for (int mt = 0; mt < 4; mt++)
#pragma unroll
                    for (int nt = 0; nt < 4; nt++)
                        mma_f16(acc[mt][nt], fa + mt * 4, fb + nt * 2);
            }
        }
        buf = (buf + 1 == PIPEN) ? 0 : buf + 1;
    }

    // ---- epilogue ----
    const int er = l >> 2;            // 0..7
    const int ec = (l & 3) * 2;       // 0,2,4,6
#pragma unroll
    for (int mt = 0; mt < 4; mt++) {
#pragma unroll
        for (int nt = 0; nt < 4; nt++) {
            const int m0 = bm + wm * 64 + mt * 16 + er;
            const int n0 = bn + wn * 32 + nt * 8 + ec;
            float v0 = acc[mt][nt][0], v1 = acc[mt][nt][1];
            float v2 = acc[mt][nt][2], v3 = acc[mt][nt][3];
            if (SIG) {
                v0 = 1.0f / (1.0f + __expf(-v0));
                v1 = 1.0f / (1.0f + __expf(-v1));
                v2 = 1.0f / (1.0f + __expf(-v2));
                v3 = 1.0f / (1.0f + __expf(-v3));
            }
            *(float2*)(C + (size_t)m0 * DD + n0)       = make_float2(v0, v1);
            *(float2*)(C + (size_t)(m0 + 8) * DD + n0) = make_float2(v2, v3);
        }
    }
}

// Fused k/v/r projection launch: blockIdx.z selects the GEMM.
// z=0: k (3-pass, PIPE=3), z=1: v (2-pass, PIPE=4), z=2: r (2-pass + sigmoid)
__global__ void __launch_bounds__(256, 2)
gemm_kvr(const __half* __restrict__ xkh, const __half* __restrict__ xkl,
         const __half* __restrict__ xvh, const __half* __restrict__ xvl,
         const __half* __restrict__ xrh, const __half* __restrict__ xrl,
         const __half* __restrict__ whk, const __half* __restrict__ wlk,
         const __half* __restrict__ whv, const __half* __restrict__ whr,
         float* __restrict__ gk, float* __restrict__ gv, float* __restrict__ gr)
{
    extern __shared__ char smem[];
    if (blockIdx.z == 0)
        gemm_body<3, 3, false>(xkh, xkl, whk, wlk, gk, smem);
    else if (blockIdx.z == 1)
        gemm_body<2, 4, false>(xvh, xvl, whv, nullptr, gv, smem);
    else
        gemm_body<2, 4, true>(xrh, xrl, whr, nullptr, gr, smem);
}

// Output projection (2-pass)
__global__ void __launch_bounds__(256, 2)
gemm_o(const __half* __restrict__ Ah, const __half* __restrict__ Al,
       const __half* __restrict__ Wh, float* __restrict__ C)
{
    extern __shared__ char smem[];
    gemm_body<2, 4, false>(Ah, Al, Wh, nullptr, C, smem);
}

// ---------------------------------------------------------------------------
// Conversion: token-shift mix + fp16 hi/lo split for the three projections
// ---------------------------------------------------------------------------
__global__ void conv_x(const float* __restrict__ x,
                       const float* __restrict__ mk, const float* __restrict__ mv,
                       const float* __restrict__ mr,
                       __half* __restrict__ kh, __half* __restrict__ kl,
                       __half* __restrict__ vh, __half* __restrict__ vl,
                       __half* __restrict__ rh, __half* __restrict__ rl)
{
    const size_t gid = (size_t)blockIdx.x * blockDim.x + threadIdx.x;
    const size_t idx = gid * 4;
    const int d = (int)(idx % DD);
    const size_t m = idx / DD;
    const int lpos = (int)(m & (LL - 1));

    const float4 xc = *(const float4*)(x + idx);
    float4 xp = make_float4(0.f, 0.f, 0.f, 0.f);
    if (lpos != 0) xp = *(const float4*)(x + idx - DD);

    const float xcv[4] = {xc.x, xc.y, xc.z, xc.w};
    const float xpv[4] = {xp.x, xp.y, xp.z, xp.w};

    const float* mixes[3] = {mk, mv, mr};
    __half* outh[3] = {kh, vh, rh};
    __half* outl[3] = {kl, vl, rl};

#pragma unroll
    for (int s = 0; s < 3; s++) {
        const float4 mx = *(const float4*)(mixes[s] + d);
        const float mxv[4] = {mx.x, mx.y, mx.z, mx.w};
        unsigned short hh[4], ll2[4];
#pragma unroll
        for (int j = 0; j < 4; j++) {
            const float a = xcv[j] * mxv[j] + xpv[j] * (1.0f - mxv[j]);
            __half h, lo;
            split1(a, h, lo);
            hh[j] = __half_as_ushort(h);
            ll2[j] = __half_as_ushort(lo);
        }
        *(ushort4*)(outh[s] + idx) = make_ushort4(hh[0], hh[1], hh[2], hh[3]);
        *(ushort4*)(outl[s] + idx) = make_ushort4(ll2[0], ll2[1], ll2[2], ll2[3]);
    }
}

// All 4 weight matrices in one kernel (fp16 hi/lo)
__global__ void conv_w_all(const float* __restrict__ W0, const float* __restrict__ W1,
                           const float* __restrict__ W2, const float* __restrict__ W3,
                           __half* __restrict__ WH, __half* __restrict__ WL)
{
    constexpr size_t WS = (size_t)DD * DD;
    const size_t gid = (size_t)blockIdx.x * blockDim.x + threadIdx.x;
    const size_t idx = gid * 4;                 // over 4*WS elements
    const int mat = (int)(idx / WS);
    const size_t off = idx % WS;
    const float* W = (mat == 0) ? W0 : (mat == 1) ? W1 : (mat == 2) ? W2 : W3;

    const float4 w4 = *(const float4*)(W + off);
    const float wv[4] = {w4.x, w4.y, w4.z, w4.w};
    unsigned short hh[4], ll2[4];
#pragma unroll
    for (int j = 0; j < 4; j++) {
        __half h, lo;
        split1(wv[j], h, lo);
        hh[j] = __half_as_ushort(h);
        ll2[j] = __half_as_ushort(lo);
    }
    *(ushort4*)(WH + idx) = make_ushort4(hh[0], hh[1], hh[2], hh[3]);
    *(ushort4*)(WL + idx) = make_ushort4(ll2[0], ll2[1], ll2[2], ll2[3]);
}

// ---------------------------------------------------------------------------
// WKV scan (chunk-parallel affine recurrence), NC=64 chunks
// ---------------------------------------------------------------------------
__global__ void wkv_phase1(const float* __restrict__ K_,
                           const float* __restrict__ V_,
                           const float* __restrict__ td,
                           float* __restrict__ SA,
                           float* __restrict__ SB)
{
    const int gid = blockIdx.x * blockDim.x + threadIdx.x;
    const int d = gid % DD;
    const int b = (gid / DD) % BB;
    const int c = gid / (DD * BB);

    const float w = -expf(td[d]);
    const float decay = expf(w);

    size_t base = ((size_t)(b * LL + c * CL)) * DD + d;
    float sa = 0.0f, sb = 0.0f;
#pragma unroll 4
    for (int t = 0; t < CL; t++) {
        const float kt = K_[base];
        const float vt = V_[base];
        const float ek = expf(kt);
        sa = decay * sa + ek * vt;
        sb = decay * sb + ek;
        base += DD;
    }
    SA[gid] = sa;
    SB[gid] = sb;
}

__global__ void wkv_phase2(const float* __restrict__ SA,
                           const float* __restrict__ SB,
                           const float* __restrict__ td,
                           float* __restrict__ AIN,
                           float* __restrict__ BIN)
{
    const int gid = blockIdx.x * blockDim.x + threadIdx.x;
    const int d = gid % DD;
    const int b = gid / DD;

    const float w = -expf(td[d]);
    const float dpow = expf(w * (float)CL);

    float a = 0.0f, bs = 0.0f;
#pragma unroll
    for (int c = 0; c < NC; c++) {
        const size_t sidx = ((size_t)c * BB + b) * DD + d;
        AIN[sidx] = a;
        BIN[sidx] = bs;
        a  = dpow * a  + SA[sidx];
        bs = dpow * bs + SB[sidx];
    }
}

__global__ void wkv_phase3(const float* __restrict__ K_,
                           const float* __restrict__ V_,
                           const float* __restrict__ td,
                           const float* __restrict__ tf,
                           const float* __restrict__ AIN,
                           const float* __restrict__ BIN,
                           const float* __restrict__ R,
                           __half* __restrict__ RWH,
                           __half* __restrict__ RWL)
{
    const int gid = blockIdx.x * blockDim.x + threadIdx.x;
    const int d = gid % DD;
    const int b = (gid / DD) % BB;
    const int c = gid / (DD * BB);

    const float w = -expf(td[d]);
    const float decay = expf(w);
    const float u = tf[d];

    float a  = AIN[gid];
    float bs = BIN[gid];

    size_t base = ((size_t)(b * LL + c * CL)) * DD + d;
#pragma unroll 4
    for (int t = 0; t < CL; t++) {
        const float kt = K_[base];
        const float vt = V_[base];
        const float eku = expf(u + kt);
        const float wkv = (a + eku * vt) / fmaxf(bs + eku, 1e-6f);
        const float ek = expf(kt);
        const float rw = R[base] * wkv;
        __half h, lo;
        split1(rw, h, lo);
        RWH[base] = h;
        RWL[base] = lo;
        a  = decay * a  + ek * vt;
        bs = decay * bs + ek;
        base += DD;
    }
}

// ---------------------------------------------------------------------------
extern "C" void kernel_launch(void* const* d_in, const int* in_sizes, int n_in,
                              void* d_out, int out_size)
{
    const float* x  = (const float*)d_in[0];
    const float* td = (const float*)d_in[1];
    const float* tf = (const float*)d_in[2];
    const float* mk = (const float*)d_in[3];
    const float* mv = (const float*)d_in[4];
    const float* mr = (const float*)d_in[5];
    const float* Wk = (const float*)d_in[6];
    const float* Wv = (const float*)d_in[7];
    const float* Wr = (const float*)d_in[8];
    const float* Wo = (const float*)d_in[9];
    float* out = (float*)d_out;

    float *gk, *gv, *gr, *gsa, *gsb, *gain, *gbin;
    __half *xkh, *xkl, *xvh, *xvl, *xrh, *xrl, *rwh, *rwl, *wh, *wl;
    cudaGetSymbolAddress((void**)&gk,   g_k);
    cudaGetSymbolAddress((void**)&gv,   g_v);
    cudaGetSymbolAddress((void**)&gr,   g_r);
    cudaGetSymbolAddress((void**)&gsa,  g_sa);
    cudaGetSymbolAddress((void**)&gsb,  g_sb);
    cudaGetSymbolAddress((void**)&gain, g_ain);
    cudaGetSymbolAddress((void**)&gbin, g_bin);
    cudaGetSymbolAddress((void**)&xkh,  g_xkh);
    cudaGetSymbolAddress((void**)&xkl,  g_xkl);
    cudaGetSymbolAddress((void**)&xvh,  g_xvh);
    cudaGetSymbolAddress((void**)&xvl,  g_xvl);
    cudaGetSymbolAddress((void**)&xrh,  g_xrh);
    cudaGetSymbolAddress((void**)&xrl,  g_xrl);
    cudaGetSymbolAddress((void**)&rwh,  g_rwh);
    cudaGetSymbolAddress((void**)&rwl,  g_rwl);
    cudaGetSymbolAddress((void**)&wh,   g_wh);
    cudaGetSymbolAddress((void**)&wl,   g_wl);

    cudaFuncSetAttribute(gemm_kvr,
                         cudaFuncAttributeMaxDynamicSharedMemorySize, GEMM_SMEM);
    cudaFuncSetAttribute(gemm_o,
                         cudaFuncAttributeMaxDynamicSharedMemorySize, GEMM_SMEM);

    const size_t WSTRIDE = (size_t)DD * DD;

    // launch 0: conv_x, 1: conv_w_all
    conv_x<<<(int)(((size_t)MM * DD / 4) / 256), 256>>>(x, mk, mv, mr,
                                                        xkh, xkl, xvh, xvl, xrh, xrl);
    conv_w_all<<<(int)((4 * WSTRIDE / 4) / 256), 256>>>(Wk, Wv, Wr, Wo, wh, wl);

    // launch 2: fused k/v/r projections (3072 CTAs -> ~10.4 waves)
    const dim3 ggz(DD / 128, MM / 128, 3);
    gemm_kvr<<<ggz, 256, GEMM_SMEM>>>(xkh, xkl, xvh, xvl, xrh, xrl,
                                      wh + 0 * WSTRIDE, wl + 0 * WSTRIDE,
                                      wh + 1 * WSTRIDE, wh + 2 * WSTRIDE,
                                      gk, gv, gr);

    // launches 3-5: wkv scan
    wkv_phase1<<<(NC * BB * DD) / 256, 256>>>(gk, gv, td, gsa, gsb);
    wkv_phase2<<<(BB * DD) / 256, 256>>>(gsa, gsb, td, gain, gbin);
    wkv_phase3<<<(NC * BB * DD) / 256, 256>>>(gk, gv, td, tf, gain, gbin, gr, rwh, rwl);

    // launch 6: output projection (2-pass)
    const dim3 gg(DD / 128, MM / 128);
    gemm_o<<<gg, 256, GEMM_SMEM>>>(rwh, rwl, wh + 3 * WSTRIDE, out);
}

// round 12
// speedup vs baseline: 1.3055x; 1.0870x over previous
#include <cuda_runtime.h>
#include <cuda_fp16.h>
#include <math.h>
#include <cstdint>
#include <cstddef>

// Problem constants
constexpr int BB = 4;
constexpr int LL = 4096;
constexpr int DD = 1024;
constexpr int MM = BB * LL;           // 16384 rows
constexpr int NC = 64;                // scan chunks
constexpr int CL = LL / NC;           // 64 steps per chunk

// ---------------------------------------------------------------------------
// Static device scratch (no allocations allowed)
// ---------------------------------------------------------------------------
__device__ float g_k[(size_t)MM * DD];
__device__ float g_v[(size_t)MM * DD];
__device__ float g_r[(size_t)MM * DD];

__device__ __half g_xkh[(size_t)MM * DD];
__device__ __half g_xkl[(size_t)MM * DD];
__device__ __half g_xvh[(size_t)MM * DD];
__device__ __half g_xvl[(size_t)MM * DD];
__device__ __half g_xrh[(size_t)MM * DD];
__device__ __half g_xrl[(size_t)MM * DD];
__device__ __half g_rwh[(size_t)MM * DD];
__device__ __half g_rwl[(size_t)MM * DD];

__device__ __half g_wh[4][(size_t)DD * DD];

__device__ float g_sa[NC * BB * DD];
__device__ float g_sb[NC * BB * DD];
__device__ float g_ain[NC * BB * DD];
__device__ float g_bin[NC * BB * DD];

// ---------------------------------------------------------------------------
// PTX helpers (arch-portable: cp.async / ldmatrix / mma.sync)
// ---------------------------------------------------------------------------
__device__ __forceinline__ uint32_t smem_u32(const void* p) {
    uint32_t a;
    asm("{ .reg .u64 t; cvta.to.shared.u64 t, %1; cvt.u32.u64 %0, t; }"
        : "=r"(a) : "l"(p));
    return a;
}

__device__ __forceinline__ void cp16(uint32_t dst, const void* src) {
    asm volatile("cp.async.cg.shared.global [%0], [%1], 16;"
                 :: "r"(dst), "l"(src) : "memory");
}

__device__ __forceinline__ void cp_commit() {
    asm volatile("cp.async.commit_group;" ::: "memory");
}

template <int N>
__device__ __forceinline__ void cp_wait() {
    asm volatile("cp.async.wait_group %0;" :: "n"(N) : "memory");
}

__device__ __forceinline__ void ldsm4(uint32_t* r, uint32_t addr) {
    asm volatile("ldmatrix.sync.aligned.m8n8.x4.shared.b16 {%0,%1,%2,%3}, [%4];"
                 : "=r"(r[0]), "=r"(r[1]), "=r"(r[2]), "=r"(r[3]) : "r"(addr));
}

__device__ __forceinline__ void mma_f16(float* d, const uint32_t* a, const uint32_t* b) {
    asm volatile(
        "mma.sync.aligned.m16n8k16.row.col.f32.f16.f16.f32 "
        "{%0,%1,%2,%3}, {%4,%5,%6,%7}, {%8,%9}, {%0,%1,%2,%3};"
        : "+f"(d[0]), "+f"(d[1]), "+f"(d[2]), "+f"(d[3])
        : "r"(a[0]), "r"(a[1]), "r"(a[2]), "r"(a[3]), "r"(b[0]), "r"(b[1]));
}

__device__ __forceinline__ void split1(float a, __half& h, __half& l) {
    h = __float2half_rn(a);
    l = __float2half_rn(a - __half2float(h));
}

// Swizzled smem offset for a [128 x 32] fp16 tile (rows of 4 x 16B chunks).
// 128B lines hold two rows; 8 chunk-positions per line XORed with line&7.
// Conflict-free for ldmatrix (8 consecutive rows, fixed chunk col).
__device__ __forceinline__ uint32_t phys(int r, int c) {
    return (uint32_t)((r >> 1) * 128 + ((((r & 1) * 4 + c) ^ ((r >> 1) & 7)) * 16));
}

// ---------------------------------------------------------------------------
// fp16 split GEMM body via mma.sync:  C[m][n] = sum_k A[m][k]*W[n][k]
//   C = Ah*Wh + Al*Wh = (Ah+Al)*Wh    (drops A*Wl: W-quant error ~2.8e-4 RMS)
// CTA tile 128x128, BK=32, 256 threads (8 warps, 2M x 4N).
// 4-stage ring, 24KB/stage -> 96KB -> 2 CTA/SM (the proven R9 config).
// Pass-major MMA order: same-acc RAW distance = 16 MMAs.
// ---------------------------------------------------------------------------
constexpr int TILE_BYTES = 128 * 32 * 2;           // 8192
constexpr int PIPE = 4;
constexpr int NSTAGE = DD / 32;                    // 32
constexpr int SBYTES = 3 * TILE_BYTES;             // 24576
constexpr int GEMM_SMEM = PIPE * SBYTES;           // 98304

template <bool SIG>
__device__ __forceinline__ void gemm_body(
    const __half* __restrict__ Ah, const __half* __restrict__ Al,
    const __half* __restrict__ Wh, float* __restrict__ C, char* smem)
{
    constexpr int OFF_AH = 0;
    constexpr int OFF_AL = TILE_BYTES;
    constexpr int OFF_WH = 2 * TILE_BYTES;

    const uint32_t sb = smem_u32(smem);
    const int tid = threadIdx.x;
    const int wid = tid >> 5;
    const int l   = tid & 31;
    const int wm  = wid & 1;          // 0..1 (M)
    const int wn  = wid >> 1;         // 0..3 (N)
    const int bm  = blockIdx.y * 128;
    const int bn  = blockIdx.x * 128;

    // ---- loader mapping: each thread copies 2 x 16B chunks per tile ----
    const int lr = tid >> 1;                   // 0..127
    const int lc0 = (tid & 1) * 2;             // chunk 0 or 2
    const size_t arow = (size_t)(bm + lr) * DD;
    const size_t wrow = (size_t)(bn + lr) * DD;
    const uint32_t sw0 = phys(lr, lc0);
    const uint32_t sw1 = phys(lr, lc0 + 1);

    float acc[4][4][4];
#pragma unroll
    for (int i = 0; i < 4; i++)
#pragma unroll
        for (int j = 0; j < 4; j++)
#pragma unroll
            for (int e = 0; e < 4; e++) acc[i][j][e] = 0.0f;

    auto load_stage = [&](int buf, int kc) {
        const uint32_t base = sb + buf * SBYTES;
        const __half* pa_h = Ah + arow + kc + lc0 * 8;
        const __half* pa_l = Al + arow + kc + lc0 * 8;
        const __half* pw_h = Wh + wrow + kc + lc0 * 8;
        cp16(base + OFF_AH + sw0, pa_h);
        cp16(base + OFF_AH + sw1, pa_h + 8);
        cp16(base + OFF_AL + sw0, pa_l);
        cp16(base + OFF_AL + sw1, pa_l + 8);
        cp16(base + OFF_WH + sw0, pw_h);
        cp16(base + OFF_WH + sw1, pw_h + 8);
    };

    // ---- ldmatrix lane-address components ----
    const int ra = wm * 64 + (l & 7) + ((l >> 3) & 1) * 8;   // + mt*16
    const int ca = (l >> 4) & 1;                              // + ks*2
    const int rb = wn * 32 + (l & 7) + ((l >> 4) & 1) * 8;   // + nt2*16
    const int cb = (l >> 3) & 1;                              // + ks*2

    // ---- preload PIPE-1 stages ----
#pragma unroll
    for (int i = 0; i < PIPE - 1; i++) {
        load_stage(i, i * 32);
        cp_commit();
    }

    int buf = 0;
    for (int s = 0; s < NSTAGE; s++) {
        cp_wait<PIPE - 2>();
        __syncthreads();

        if (s + PIPE - 1 < NSTAGE)
            load_stage((s + PIPE - 1) & (PIPE - 1), (s + PIPE - 1) * 32);
        cp_commit();

        const uint32_t base = sb + buf * SBYTES;
#pragma unroll
        for (int ks = 0; ks < 2; ks++) {
            uint32_t fa[16], fl[16], fb[8];
#pragma unroll
            for (int mt = 0; mt < 4; mt++) {
                const uint32_t off = phys(ra + mt * 16, ks * 2 + ca);
                ldsm4(fa + mt * 4, base + OFF_AH + off);
                ldsm4(fl + mt * 4, base + OFF_AL + off);
            }
#pragma unroll
            for (int nt2 = 0; nt2 < 2; nt2++) {
                const uint32_t off = phys(rb + nt2 * 16, ks * 2 + cb);
                ldsm4(fb + nt2 * 4, base + OFF_WH + off);
            }
            // pass-major: same-acc MMAs are 16 apart (no RAW back-pressure)
#pragma unroll
            for (int mt = 0; mt < 4; mt++)
#pragma unroll
                for (int nt = 0; nt < 4; nt++)
                    mma_f16(acc[mt][nt], fa + mt * 4, fb + nt * 2);
#pragma unroll
            for (int mt = 0; mt < 4; mt++)
#pragma unroll
                for (int nt = 0; nt < 4; nt++)
                    mma_f16(acc[mt][nt], fl + mt * 4, fb + nt * 2);
        }
        buf = (buf + 1) & (PIPE - 1);
    }

    // ---- epilogue ----
    const int er = l >> 2;            // 0..7
    const int ec = (l & 3) * 2;       // 0,2,4,6
#pragma unroll
    for (int mt = 0; mt < 4; mt++) {
#pragma unroll
        for (int nt = 0; nt < 4; nt++) {
            const int m0 = bm + wm * 64 + mt * 16 + er;
            const int n0 = bn + wn * 32 + nt * 8 + ec;
            float v0 = acc[mt][nt][0], v1 = acc[mt][nt][1];
            float v2 = acc[mt][nt][2], v3 = acc[mt][nt][3];
            if (SIG) {
                v0 = 1.0f / (1.0f + __expf(-v0));
                v1 = 1.0f / (1.0f + __expf(-v1));
                v2 = 1.0f / (1.0f + __expf(-v2));
                v3 = 1.0f / (1.0f + __expf(-v3));
            }
            *(float2*)(C + (size_t)m0 * DD + n0)       = make_float2(v0, v1);
            *(float2*)(C + (size_t)(m0 + 8) * DD + n0) = make_float2(v2, v3);
        }
    }
}

// Fused k/v/r projection launch: blockIdx.z selects the GEMM.
__global__ void __launch_bounds__(256, 2)
gemm_kvr(const __half* __restrict__ xkh, const __half* __restrict__ xkl,
         const __half* __restrict__ xvh, const __half* __restrict__ xvl,
         const __half* __restrict__ xrh, const __half* __restrict__ xrl,
         const __half* __restrict__ whk, const __half* __restrict__ whv,
         const __half* __restrict__ whr,
         float* __restrict__ gk, float* __restrict__ gv, float* __restrict__ gr)
{
    extern __shared__ char smem[];
    if (blockIdx.z == 0)
        gemm_body<false>(xkh, xkl, whk, gk, smem);
    else if (blockIdx.z == 1)
        gemm_body<false>(xvh, xvl, whv, gv, smem);
    else
        gemm_body<true>(xrh, xrl, whr, gr, smem);
}

// Output projection
__global__ void __launch_bounds__(256, 2)
gemm_o(const __half* __restrict__ Ah, const __half* __restrict__ Al,
       const __half* __restrict__ Wh, float* __restrict__ C)
{
    extern __shared__ char smem[];
    gemm_body<false>(Ah, Al, Wh, C, smem);
}

// ---------------------------------------------------------------------------
// Conversion: token-shift mix + fp16 hi/lo split for the three projections
// ---------------------------------------------------------------------------
__global__ void conv_x(const float* __restrict__ x,
                       const float* __restrict__ mk, const float* __restrict__ mv,
                       const float* __restrict__ mr,
                       __half* __restrict__ kh, __half* __restrict__ kl,
                       __half* __restrict__ vh, __half* __restrict__ vl,
                       __half* __restrict__ rh, __half* __restrict__ rl)
{
    const size_t gid = (size_t)blockIdx.x * blockDim.x + threadIdx.x;
    const size_t idx = gid * 4;
    const int d = (int)(idx % DD);
    const size_t m = idx / DD;
    const int lpos = (int)(m & (LL - 1));

    const float4 xc = *(const float4*)(x + idx);
    float4 xp = make_float4(0.f, 0.f, 0.f, 0.f);
    if (lpos != 0) xp = *(const float4*)(x + idx - DD);

    const float xcv[4] = {xc.x, xc.y, xc.z, xc.w};
    const float xpv[4] = {xp.x, xp.y, xp.z, xp.w};

    const float* mixes[3] = {mk, mv, mr};
    __half* outh[3] = {kh, vh, rh};
    __half* outl[3] = {kl, vl, rl};

#pragma unroll
    for (int s = 0; s < 3; s++) {
        const float4 mx = *(const float4*)(mixes[s] + d);
        const float mxv[4] = {mx.x, mx.y, mx.z, mx.w};
        unsigned short hh[4], ll2[4];
#pragma unroll
        for (int j = 0; j < 4; j++) {
            const float a = xcv[j] * mxv[j] + xpv[j] * (1.0f - mxv[j]);
            __half h, lo;
            split1(a, h, lo);
            hh[j] = __half_as_ushort(h);
            ll2[j] = __half_as_ushort(lo);
        }
        *(ushort4*)(outh[s] + idx) = make_ushort4(hh[0], hh[1], hh[2], hh[3]);
        *(ushort4*)(outl[s] + idx) = make_ushort4(ll2[0], ll2[1], ll2[2], ll2[3]);
    }
}

// All 4 weight matrices -> fp16 (hi only; 2-pass GEMM drops the Wl term)
__global__ void conv_w_all(const float* __restrict__ W0, const float* __restrict__ W1,
                           const float* __restrict__ W2, const float* __restrict__ W3,
                           __half* __restrict__ WH)
{
    constexpr size_t WS = (size_t)DD * DD;
    const size_t gid = (size_t)blockIdx.x * blockDim.x + threadIdx.x;
    const size_t idx = gid * 4;                 // over 4*WS elements
    const int mat = (int)(idx / WS);
    const size_t off = idx % WS;
    const float* W = (mat == 0) ? W0 : (mat == 1) ? W1 : (mat == 2) ? W2 : W3;

    const float4 w4 = *(const float4*)(W + off);
    unsigned short hh[4];
    hh[0] = __half_as_ushort(__float2half_rn(w4.x));
    hh[1] = __half_as_ushort(__float2half_rn(w4.y));
    hh[2] = __half_as_ushort(__float2half_rn(w4.z));
    hh[3] = __half_as_ushort(__float2half_rn(w4.w));
    *(ushort4*)(WH + idx) = make_ushort4(hh[0], hh[1], hh[2], hh[3]);
}

// ---------------------------------------------------------------------------
// WKV scan (chunk-parallel affine recurrence), NC=64 chunks
// ---------------------------------------------------------------------------
__global__ void wkv_phase1(const float* __restrict__ K_,
                           const float* __restrict__ V_,
                           const float* __restrict__ td,
                           float* __restrict__ SA,
                           float* __restrict__ SB)
{
    const int gid = blockIdx.x * blockDim.x + threadIdx.x;
    const int d = gid % DD;
    const int b = (gid / DD) % BB;
    const int c = gid / (DD * BB);

    const float w = -expf(td[d]);
    const float decay = expf(w);

    size_t base = ((size_t)(b * LL + c * CL)) * DD + d;
    float sa = 0.0f, sb = 0.0f;
#pragma unroll 4
    for (int t = 0; t < CL; t++) {
        const float kt = K_[base];
        const float vt = V_[base];
        const float ek = expf(kt);
        sa = decay * sa + ek * vt;
        sb = decay * sb + ek;
        base += DD;
    }
    SA[gid] = sa;
    SB[gid] = sb;
}

__global__ void wkv_phase2(const float* __restrict__ SA,
                           const float* __restrict__ SB,
                           const float* __restrict__ td,
                           float* __restrict__ AIN,
                           float* __restrict__ BIN)
{
    const int gid = blockIdx.x * blockDim.x + threadIdx.x;
    const int d = gid % DD;
    const int b = gid / DD;

    const float w = -expf(td[d]);
    const float dpow = expf(w * (float)CL);

    float a = 0.0f, bs = 0.0f;
#pragma unroll
    for (int c = 0; c < NC; c++) {
        const size_t sidx = ((size_t)c * BB + b) * DD + d;
        AIN[sidx] = a;
        BIN[sidx] = bs;
        a  = dpow * a  + SA[sidx];
        bs = dpow * bs + SB[sidx];
    }
}

__global__ void wkv_phase3(const float* __restrict__ K_,
                           const float* __restrict__ V_,
                           const float* __restrict__ td,
                           const float* __restrict__ tf,
                           const float* __restrict__ AIN,
                           const float* __restrict__ BIN,
                           const float* __restrict__ R,
                           __half* __restrict__ RWH,
                           __half* __restrict__ RWL)
{
    const int gid = blockIdx.x * blockDim.x + threadIdx.x;
    const int d = gid % DD;
    const int b = (gid / DD) % BB;
    const int c = gid / (DD * BB);

    const float w = -expf(td[d]);
    const float decay = expf(w);
    const float u = tf[d];

    float a  = AIN[gid];
    float bs = BIN[gid];

    size_t base = ((size_t)(b * LL + c * CL)) * DD + d;
#pragma unroll 4
    for (int t = 0; t < CL; t++) {
        const float kt = K_[base];
        const float vt = V_[base];
        const float eku = expf(u + kt);
        const float wkv = (a + eku * vt) / fmaxf(bs + eku, 1e-6f);
        const float ek = expf(kt);
        const float rw = R[base] * wkv;
        __half h, lo;
        split1(rw, h, lo);
        RWH[base] = h;
        RWL[base] = lo;
        a  = decay * a  + ek * vt;
        bs = decay * bs + ek;
        base += DD;
    }
}

// ---------------------------------------------------------------------------
extern "C" void kernel_launch(void* const* d_in, const int* in_sizes, int n_in,
                              void* d_out, int out_size)
{
    const float* x  = (const float*)d_in[0];
    const float* td = (const float*)d_in[1];
    const float* tf = (const float*)d_in[2];
    const float* mk = (const float*)d_in[3];
    const float* mv = (const float*)d_in[4];
    const float* mr = (const float*)d_in[5];
    const float* Wk = (const float*)d_in[6];
    const float* Wv = (const float*)d_in[7];
    const float* Wr = (const float*)d_in[8];
    const float* Wo = (const float*)d_in[9];
    float* out = (float*)d_out;

    float *gk, *gv, *gr, *gsa, *gsb, *gain, *gbin;
    __half *xkh, *xkl, *xvh, *xvl, *xrh, *xrl, *rwh, *rwl, *wh;
    cudaGetSymbolAddress((void**)&gk,   g_k);
    cudaGetSymbolAddress((void**)&gv,   g_v);
    cudaGetSymbolAddress((void**)&gr,   g_r);
    cudaGetSymbolAddress((void**)&gsa,  g_sa);
    cudaGetSymbolAddress((void**)&gsb,  g_sb);
    cudaGetSymbolAddress((void**)&gain, g_ain);
    cudaGetSymbolAddress((void**)&gbin, g_bin);
    cudaGetSymbolAddress((void**)&xkh,  g_xkh);
    cudaGetSymbolAddress((void**)&xkl,  g_xkl);
    cudaGetSymbolAddress((void**)&xvh,  g_xvh);
    cudaGetSymbolAddress((void**)&xvl,  g_xvl);
    cudaGetSymbolAddress((void**)&xrh,  g_xrh);
    cudaGetSymbolAddress((void**)&xrl,  g_xrl);
    cudaGetSymbolAddress((void**)&rwh,  g_rwh);
    cudaGetSymbolAddress((void**)&rwl,  g_rwl);
    cudaGetSymbolAddress((void**)&wh,   g_wh);

    cudaFuncSetAttribute(gemm_kvr,
                         cudaFuncAttributeMaxDynamicSharedMemorySize, GEMM_SMEM);
    cudaFuncSetAttribute(gemm_o,
                         cudaFuncAttributeMaxDynamicSharedMemorySize, GEMM_SMEM);

    const size_t WSTRIDE = (size_t)DD * DD;

    // launch 0: conv_x, 1: conv_w_all
    conv_x<<<(int)(((size_t)MM * DD / 4) / 256), 256>>>(x, mk, mv, mr,
                                                        xkh, xkl, xvh, xvl, xrh, xrl);
    conv_w_all<<<(int)((4 * WSTRIDE / 4) / 256), 256>>>(Wk, Wv, Wr, Wo, wh);

    // launch 2: fused k/v/r projections (3072 CTAs)
    const dim3 ggz(DD / 128, MM / 128, 3);
    gemm_kvr<<<ggz, 256, GEMM_SMEM>>>(xkh, xkl, xvh, xvl, xrh, xrl,
                                      wh + 0 * WSTRIDE, wh + 1 * WSTRIDE,
                                      wh + 2 * WSTRIDE,
                                      gk, gv, gr);

    // launches 3-5: wkv scan
    wkv_phase1<<<(NC * BB * DD) / 256, 256>>>(gk, gv, td, gsa, gsb);
    wkv_phase2<<<(BB * DD) / 256, 256>>>(gsa, gsb, td, gain, gbin);
    wkv_phase3<<<(NC * BB * DD) / 256, 256>>>(gk, gv, td, tf, gain, gbin, gr, rwh, rwl);

    // launch 6: output projection
    const dim3 gg(DD / 128, MM / 128);
    gemm_o<<<gg, 256, GEMM_SMEM>>>(rwh, rwl, wh + 3 * WSTRIDE, out);
}

// round 14
// speedup vs baseline: 1.8787x; 1.4391x over previous
#include <cuda_runtime.h>
#include <cuda_fp16.h>
#include <math.h>
#include <cstdint>
#include <cstddef>

// Problem constants
constexpr int BB = 4;
constexpr int LL = 4096;
constexpr int DD = 1024;
constexpr int MM = BB * LL;           // 16384 rows
constexpr int NC = 64;                // scan chunks
constexpr int CL = LL / NC;           // 64 steps per chunk

// ---------------------------------------------------------------------------
// Static device scratch (no allocations allowed)
// ---------------------------------------------------------------------------
__device__ float g_k[(size_t)MM * DD];
__device__ float g_v[(size_t)MM * DD];
__device__ float g_r[(size_t)MM * DD];

__device__ __half g_xkh[(size_t)MM * DD];
__device__ __half g_xkl[(size_t)MM * DD];
__device__ __half g_xvh[(size_t)MM * DD];
__device__ __half g_xrh[(size_t)MM * DD];
__device__ __half g_rwh[(size_t)MM * DD];

__device__ __half g_wh[4][(size_t)DD * DD];

__device__ float g_sa[NC * BB * DD];
__device__ float g_sb[NC * BB * DD];
__device__ float g_ain[NC * BB * DD];
__device__ float g_bin[NC * BB * DD];

// ---------------------------------------------------------------------------
// PTX helpers (arch-portable: cp.async / ldmatrix / mma.sync)
// ---------------------------------------------------------------------------
__device__ __forceinline__ uint32_t smem_u32(const void* p) {
    uint32_t a;
    asm("{ .reg .u64 t; cvta.to.shared.u64 t, %1; cvt.u32.u64 %0, t; }"
        : "=r"(a) : "l"(p));
    return a;
}

__device__ __forceinline__ void cp16(uint32_t dst, const void* src) {
    asm volatile("cp.async.cg.shared.global [%0], [%1], 16;"
                 :: "r"(dst), "l"(src) : "memory");
}

__device__ __forceinline__ void cp_commit() {
    asm volatile("cp.async.commit_group;" ::: "memory");
}

template <int N>
__device__ __forceinline__ void cp_wait() {
    asm volatile("cp.async.wait_group %0;" :: "n"(N) : "memory");
}

__device__ __forceinline__ void ldsm4(uint32_t* r, uint32_t addr) {
    asm volatile("ldmatrix.sync.aligned.m8n8.x4.shared.b16 {%0,%1,%2,%3}, [%4];"
                 : "=r"(r[0]), "=r"(r[1]), "=r"(r[2]), "=r"(r[3]) : "r"(addr));
}

__device__ __forceinline__ void mma_f16(float* d, const uint32_t* a, const uint32_t* b) {
    asm volatile(
        "mma.sync.aligned.m16n8k16.row.col.f32.f16.f16.f32 "
        "{%0,%1,%2,%3}, {%4,%5,%6,%7}, {%8,%9}, {%0,%1,%2,%3};"
        : "+f"(d[0]), "+f"(d[1]), "+f"(d[2]), "+f"(d[3])
        : "r"(a[0]), "r"(a[1]), "r"(a[2]), "r"(a[3]), "r"(b[0]), "r"(b[1]));
}

__device__ __forceinline__ void split1(float a, __half& h, __half& l) {
    h = __float2half_rn(a);
    l = __float2half_rn(a - __half2float(h));
}

// Swizzled smem offset for a [128 x 32] fp16 tile (rows of 4 x 16B chunks).
// 128B lines hold two rows; 8 chunk-positions per line XORed with line&7.
// Conflict-free for ldmatrix (8 consecutive rows, fixed chunk col).
__device__ __forceinline__ uint32_t phys(int r, int c) {
    return (uint32_t)((r >> 1) * 128 + ((((r & 1) * 4 + c) ^ ((r >> 1) & 7)) * 16));
}

// ---------------------------------------------------------------------------
// fp16 GEMM body via mma.sync:  C[m][n] = sum_k A[m][k]*W[n][k]
//   NPASS=2 (PIPE=4, 24KB/stage): C = (Ah+Al)*Wh    (k projection)
//   NPASS=1 (PIPE=6, 16KB/stage): C = Ah*Wh         (v/r/o; pure fp16)
// Both rings = 96KB -> 2 CTA/SM. CTA tile 128x128, BK=32, 256 threads.
// Pass-major MMA order: same-acc RAW distance = 16 MMAs.
// ---------------------------------------------------------------------------
constexpr int TILE_BYTES = 128 * 32 * 2;           // 8192
constexpr int NSTAGE = DD / 32;                    // 32
constexpr int GEMM_SMEM = 98304;                   // 4*24KB = 6*16KB

template <int NPASS, int PIPEN, bool SIG>
__device__ __forceinline__ void gemm_body(
    const __half* __restrict__ Ah, const __half* __restrict__ Al,
    const __half* __restrict__ Wh, float* __restrict__ C, char* smem)
{
    constexpr int SBYTES = (NPASS + 1) * TILE_BYTES;
    constexpr int OFF_AH = 0;
    constexpr int OFF_AL = TILE_BYTES;              // only when NPASS==2
    constexpr int OFF_WH = NPASS * TILE_BYTES;

    const uint32_t sb = smem_u32(smem);
    const int tid = threadIdx.x;
    const int wid = tid >> 5;
    const int l   = tid & 31;
    const int wm  = wid & 1;          // 0..1 (M)
    const int wn  = wid >> 1;         // 0..3 (N)
    const int bm  = blockIdx.y * 128;
    const int bn  = blockIdx.x * 128;

    // ---- loader mapping: each thread copies 2 x 16B chunks per tile ----
    const int lr = tid >> 1;                   // 0..127
    const int lc0 = (tid & 1) * 2;             // chunk 0 or 2
    const size_t arow = (size_t)(bm + lr) * DD;
    const size_t wrow = (size_t)(bn + lr) * DD;
    const uint32_t sw0 = phys(lr, lc0);
    const uint32_t sw1 = phys(lr, lc0 + 1);

    float acc[4][4][4];
#pragma unroll
    for (int i = 0; i < 4; i++)
#pragma unroll
        for (int j = 0; j < 4; j++)
#pragma unroll
            for (int e = 0; e < 4; e++) acc[i][j][e] = 0.0f;

    auto load_stage = [&](int buf, int kc) {
        const uint32_t base = sb + buf * SBYTES;
        const __half* pa_h = Ah + arow + kc + lc0 * 8;
        const __half* pw_h = Wh + wrow + kc + lc0 * 8;
        cp16(base + OFF_AH + sw0, pa_h);
        cp16(base + OFF_AH + sw1, pa_h + 8);
        if (NPASS == 2) {
            const __half* pa_l = Al + arow + kc + lc0 * 8;
            cp16(base + OFF_AL + sw0, pa_l);
            cp16(base + OFF_AL + sw1, pa_l + 8);
        }
        cp16(base + OFF_WH + sw0, pw_h);
        cp16(base + OFF_WH + sw1, pw_h + 8);
    };

    // ---- ldmatrix lane-address components ----
    const int ra = wm * 64 + (l & 7) + ((l >> 3) & 1) * 8;   // + mt*16
    const int ca = (l >> 4) & 1;                              // + ks*2
    const int rb = wn * 32 + (l & 7) + ((l >> 4) & 1) * 8;   // + nt2*16
    const int cb = (l >> 3) & 1;                              // + ks*2

    // ---- preload PIPEN-1 stages ----
#pragma unroll
    for (int i = 0; i < PIPEN - 1; i++) {
        load_stage(i, i * 32);
        cp_commit();
    }

    int buf = 0;
    for (int s = 0; s < NSTAGE; s++) {
        cp_wait<PIPEN - 2>();
        __syncthreads();

        if (s + PIPEN - 1 < NSTAGE)
            load_stage((s + PIPEN - 1) % PIPEN, (s + PIPEN - 1) * 32);
        cp_commit();

        const uint32_t base = sb + buf * SBYTES;
#pragma unroll
        for (int ks = 0; ks < 2; ks++) {
            uint32_t fa[16], fl[16], fb[8];
#pragma unroll
            for (int mt = 0; mt < 4; mt++) {
                const uint32_t off = phys(ra + mt * 16, ks * 2 + ca);
                ldsm4(fa + mt * 4, base + OFF_AH + off);
                if (NPASS == 2) ldsm4(fl + mt * 4, base + OFF_AL + off);
            }
#pragma unroll
            for (int nt2 = 0; nt2 < 2; nt2++) {
                const uint32_t off = phys(rb + nt2 * 16, ks * 2 + cb);
                ldsm4(fb + nt2 * 4, base + OFF_WH + off);
            }
            // pass-major: same-acc MMAs are 16 apart (no RAW back-pressure)
#pragma unroll
            for (int mt = 0; mt < 4; mt++)
#pragma unroll
                for (int nt = 0; nt < 4; nt++)
                    mma_f16(acc[mt][nt], fa + mt * 4, fb + nt * 2);
            if (NPASS == 2) {
#pragma unroll
                for (int mt = 0; mt < 4; mt++)
#pragma unroll
                    for (int nt = 0; nt < 4; nt++)
                        mma_f16(acc[mt][nt], fl + mt * 4, fb + nt * 2);
            }
        }
        buf = (buf + 1 == PIPEN) ? 0 : buf + 1;
    }

    // ---- epilogue ----
    const int er = l >> 2;            // 0..7
    const int ec = (l & 3) * 2;       // 0,2,4,6
#pragma unroll
    for (int mt = 0; mt < 4; mt++) {
#pragma unroll
        for (int nt = 0; nt < 4; nt++) {
            const int m0 = bm + wm * 64 + mt * 16 + er;
            const int n0 = bn + wn * 32 + nt * 8 + ec;
            float v0 = acc[mt][nt][0], v1 = acc[mt][nt][1];
            float v2 = acc[mt][nt][2], v3 = acc[mt][nt][3];
            if (SIG) {
                v0 = 1.0f / (1.0f + __expf(-v0));
                v1 = 1.0f / (1.0f + __expf(-v1));
                v2 = 1.0f / (1.0f + __expf(-v2));
                v3 = 1.0f / (1.0f + __expf(-v3));
            }
            *(float2*)(C + (size_t)m0 * DD + n0)       = make_float2(v0, v1);
            *(float2*)(C + (size_t)(m0 + 8) * DD + n0) = make_float2(v2, v3);
        }
    }
}

// Fused k/v/r projection launch: blockIdx.z selects the GEMM.
// z=0: k (2-pass, PIPE=4), z=1: v (1-pass, PIPE=6), z=2: r (1-pass + sigmoid)
__global__ void __launch_bounds__(256, 2)
gemm_kvr(const __half* __restrict__ xkh, const __half* __restrict__ xkl,
         const __half* __restrict__ xvh, const __half* __restrict__ xrh,
         const __half* __restrict__ whk, const __half* __restrict__ whv,
         const __half* __restrict__ whr,
         float* __restrict__ gk, float* __restrict__ gv, float* __restrict__ gr)
{
    extern __shared__ char smem[];
    if (blockIdx.z == 0)
        gemm_body<2, 4, false>(xkh, xkl, whk, gk, smem);
    else if (blockIdx.z == 1)
        gemm_body<1, 6, false>(xvh, nullptr, whv, gv, smem);
    else
        gemm_body<1, 6, true>(xrh, nullptr, whr, gr, smem);
}

// Output projection (1-pass)
__global__ void __launch_bounds__(256, 2)
gemm_o(const __half* __restrict__ Ah, const __half* __restrict__ Wh,
       float* __restrict__ C)
{
    extern __shared__ char smem[];
    gemm_body<1, 6, false>(Ah, nullptr, Wh, C, smem);
}

// ---------------------------------------------------------------------------
// Conversion: token-shift mix; k gets fp16 hi/lo split, v/r hi only
// ---------------------------------------------------------------------------
__global__ void conv_x(const float* __restrict__ x,
                       const float* __restrict__ mk, const float* __restrict__ mv,
                       const float* __restrict__ mr,
                       __half* __restrict__ kh, __half* __restrict__ kl,
                       __half* __restrict__ vh, __half* __restrict__ rh)
{
    const size_t gid = (size_t)blockIdx.x * blockDim.x + threadIdx.x;
    const size_t idx = gid * 4;
    const int d = (int)(idx % DD);
    const size_t m = idx / DD;
    const int lpos = (int)(m & (LL - 1));

    const float4 xc = *(const float4*)(x + idx);
    float4 xp = make_float4(0.f, 0.f, 0.f, 0.f);
    if (lpos != 0) xp = *(const float4*)(x + idx - DD);

    const float xcv[4] = {xc.x, xc.y, xc.z, xc.w};
    const float xpv[4] = {xp.x, xp.y, xp.z, xp.w};

    // k: hi + lo
    {
        const float4 mx = *(const float4*)(mk + d);
        const float mxv[4] = {mx.x, mx.y, mx.z, mx.w};
        unsigned short hh[4], ll2[4];
#pragma unroll
        for (int j = 0; j < 4; j++) {
            const float a = xcv[j] * mxv[j] + xpv[j] * (1.0f - mxv[j]);
            __half h, lo;
            split1(a, h, lo);
            hh[j] = __half_as_ushort(h);
            ll2[j] = __half_as_ushort(lo);
        }
        *(ushort4*)(kh + idx) = make_ushort4(hh[0], hh[1], hh[2], hh[3]);
        *(ushort4*)(kl + idx) = make_ushort4(ll2[0], ll2[1], ll2[2], ll2[3]);
    }
    // v, r: hi only
    {
        const float4 mx = *(const float4*)(mv + d);
        const float mxv[4] = {mx.x, mx.y, mx.z, mx.w};
        unsigned short hh[4];
#pragma unroll
        for (int j = 0; j < 4; j++) {
            const float a = xcv[j] * mxv[j] + xpv[j] * (1.0f - mxv[j]);
            hh[j] = __half_as_ushort(__float2half_rn(a));
        }
        *(ushort4*)(vh + idx) = make_ushort4(hh[0], hh[1], hh[2], hh[3]);
    }
    {
        const float4 mx = *(const float4*)(mr + d);
        const float mxv[4] = {mx.x, mx.y, mx.z, mx.w};
        unsigned short hh[4];
#pragma unroll
        for (int j = 0; j < 4; j++) {
            const float a = xcv[j] * mxv[j] + xpv[j] * (1.0f - mxv[j]);
            hh[j] = __half_as_ushort(__float2half_rn(a));
        }
        *(ushort4*)(rh + idx) = make_ushort4(hh[0], hh[1], hh[2], hh[3]);
    }
}

// All 4 weight matrices -> fp16 (hi only)
__global__ void conv_w_all(const float* __restrict__ W0, const float* __restrict__ W1,
                           const float* __restrict__ W2, const float* __restrict__ W3,
                           __half* __restrict__ WH)
{
    constexpr size_t WS = (size_t)DD * DD;
    const size_t gid = (size_t)blockIdx.x * blockDim.x + threadIdx.x;
    const size_t idx = gid * 4;                 // over 4*WS elements
    const int mat = (int)(idx / WS);
    const size_t off = idx % WS;
    const float* W = (mat == 0) ? W0 : (mat == 1) ? W1 : (mat == 2) ? W2 : W3;

    const float4 w4 = *(const float4*)(W + off);
    unsigned short hh[4];
    hh[0] = __half_as_ushort(__float2half_rn(w4.x));
    hh[1] = __half_as_ushort(__float2half_rn(w4.y));
    hh[2] = __half_as_ushort(__float2half_rn(w4.z));
    hh[3] = __half_as_ushort(__float2half_rn(w4.w));
    *(ushort4*)(WH + idx) = make_ushort4(hh[0], hh[1], hh[2], hh[3]);
}

// ---------------------------------------------------------------------------
// WKV scan (chunk-parallel affine recurrence), NC=64 chunks
// ---------------------------------------------------------------------------
__global__ void wkv_phase1(const float* __restrict__ K_,
                           const float* __restrict__ V_,
                           const float* __restrict__ td,
                           float* __restrict__ SA,
                           float* __restrict__ SB)
{
    const int gid = blockIdx.x * blockDim.x + threadIdx.x;
    const int d = gid % DD;
    const int b = (gid / DD) % BB;
    const int c = gid / (DD * BB);

    const float w = -expf(td[d]);
    const float decay = expf(w);

    size_t base = ((size_t)(b * LL + c * CL)) * DD + d;
    float sa = 0.0f, sb = 0.0f;
#pragma unroll 4
    for (int t = 0; t < CL; t++) {
        const float kt = K_[base];
        const float vt = V_[base];
        const float ek = expf(kt);
        sa = decay * sa + ek * vt;
        sb = decay * sb + ek;
        base += DD;
    }
    SA[gid] = sa;
    SB[gid] = sb;
}

__global__ void wkv_phase2(const float* __restrict__ SA,
                           const float* __restrict__ SB,
                           const float* __restrict__ td,
                           float* __restrict__ AIN,
                           float* __restrict__ BIN)
{
    const int gid = blockIdx.x * blockDim.x + threadIdx.x;
    const int d = gid % DD;
    const int b = gid / DD;

    const float w = -expf(td[d]);
    const float dpow = expf(w * (float)CL);

    float a = 0.0f, bs = 0.0f;
#pragma unroll
    for (int c = 0; c < NC; c++) {
        const size_t sidx = ((size_t)c * BB + b) * DD + d;
        AIN[sidx] = a;
        BIN[sidx] = bs;
        a  = dpow * a  + SA[sidx];
        bs = dpow * bs + SB[sidx];
    }
}

__global__ void wkv_phase3(const float* __restrict__ K_,
                           const float* __restrict__ V_,
                           const float* __restrict__ td,
                           const float* __restrict__ tf,
                           const float* __restrict__ AIN,
                           const float* __restrict__ BIN,
                           const float* __restrict__ R,
                           __half* __restrict__ RWH)
{
    const int gid = blockIdx.x * blockDim.x + threadIdx.x;
    const int d = gid % DD;
    const int b = (gid / DD) % BB;
    const int c = gid / (DD * BB);

    const float w = -expf(td[d]);
    const float decay = expf(w);
    const float u = tf[d];

    float a  = AIN[gid];
    float bs = BIN[gid];

    size_t base = ((size_t)(b * LL + c * CL)) * DD + d;
#pragma unroll 4
    for (int t = 0; t < CL; t++) {
        const float kt = K_[base];
        const float vt = V_[base];
        const float eku = expf(u + kt);
        const float wkv = (a + eku * vt) / fmaxf(bs + eku, 1e-6f);
        const float ek = expf(kt);
        RWH[base] = __float2half_rn(R[base] * wkv);
        a  = decay * a  + ek * vt;
        bs = decay * bs + ek;
        base += DD;
    }
}

// ---------------------------------------------------------------------------
extern "C" void kernel_launch(void* const* d_in, const int* in_sizes, int n_in,
                              void* d_out, int out_size)
{
    const float* x  = (const float*)d_in[0];
    const float* td = (const float*)d_in[1];
    const float* tf = (const float*)d_in[2];
    const float* mk = (const float*)d_in[3];
    const float* mv = (const float*)d_in[4];
    const float* mr = (const float*)d_in[5];
    const float* Wk = (const float*)d_in[6];
    const float* Wv = (const float*)d_in[7];
    const float* Wr = (const float*)d_in[8];
    const float* Wo = (const float*)d_in[9];
    float* out = (float*)d_out;

    float *gk, *gv, *gr, *gsa, *gsb, *gain, *gbin;
    __half *xkh, *xkl, *xvh, *xrh, *rwh, *wh;
    cudaGetSymbolAddress((void**)&gk,   g_k);
    cudaGetSymbolAddress((void**)&gv,   g_v);
    cudaGetSymbolAddress((void**)&gr,   g_r);
    cudaGetSymbolAddress((void**)&gsa,  g_sa);
    cudaGetSymbolAddress((void**)&gsb,  g_sb);
    cudaGetSymbolAddress((void**)&gain, g_ain);
    cudaGetSymbolAddress((void**)&gbin, g_bin);
    cudaGetSymbolAddress((void**)&xkh,  g_xkh);
    cudaGetSymbolAddress((void**)&xkl,  g_xkl);
    cudaGetSymbolAddress((void**)&xvh,  g_xvh);
    cudaGetSymbolAddress((void**)&xrh,  g_xrh);
    cudaGetSymbolAddress((void**)&rwh,  g_rwh);
    cudaGetSymbolAddress((void**)&wh,   g_wh);

    cudaFuncSetAttribute(gemm_kvr,
                         cudaFuncAttributeMaxDynamicSharedMemorySize, GEMM_SMEM);
    cudaFuncSetAttribute(gemm_o,
                         cudaFuncAttributeMaxDynamicSharedMemorySize, GEMM_SMEM);

    const size_t WSTRIDE = (size_t)DD * DD;

    // launch 0: conv_x, 1: conv_w_all
    conv_x<<<(int)(((size_t)MM * DD / 4) / 256), 256>>>(x, mk, mv, mr,
                                                        xkh, xkl, xvh, xrh);
    conv_w_all<<<(int)((4 * WSTRIDE / 4) / 256), 256>>>(Wk, Wv, Wr, Wo, wh);

    // launch 2: fused k/v/r projections (3072 CTAs)
    const dim3 ggz(DD / 128, MM / 128, 3);
    gemm_kvr<<<ggz, 256, GEMM_SMEM>>>(xkh, xkl, xvh, xrh,
                                      wh + 0 * WSTRIDE, wh + 1 * WSTRIDE,
                                      wh + 2 * WSTRIDE,
                                      gk, gv, gr);

    // launches 3-5: wkv scan
    wkv_phase1<<<(NC * BB * DD) / 256, 256>>>(gk, gv, td, gsa, gsb);
    wkv_phase2<<<(BB * DD) / 256, 256>>>(gsa, gsb, td, gain, gbin);
    wkv_phase3<<<(NC * BB * DD) / 256, 256>>>(gk, gv, td, tf, gain, gbin, gr, rwh);

    // launch 6: output projection (1-pass)
    const dim3 gg(DD / 128, MM / 128);
    gemm_o<<<gg, 256, GEMM_SMEM>>>(rwh, wh + 3 * WSTRIDE, out);
}

// round 15
// speedup vs baseline: 2.1247x; 1.1309x over previous
#include <cuda_runtime.h>
#include <cuda_fp16.h>
#include <math.h>
#include <cstdint>
#include <cstddef>

// Problem constants
constexpr int BB = 4;
constexpr int LL = 4096;
constexpr int DD = 1024;
constexpr int MM = BB * LL;           // 16384 rows
constexpr int NC = 64;                // scan chunks
constexpr int CL = LL / NC;           // 64 steps per chunk

// ---------------------------------------------------------------------------
// Static device scratch (no allocations allowed)
// ---------------------------------------------------------------------------
__device__ float g_k[(size_t)MM * DD];
__device__ float g_v[(size_t)MM * DD];
__device__ float g_r[(size_t)MM * DD];

__device__ __half g_xkh[(size_t)MM * DD];
__device__ __half g_xvh[(size_t)MM * DD];
__device__ __half g_xrh[(size_t)MM * DD];
__device__ __half g_rwh[(size_t)MM * DD];

__device__ __half g_wh[4][(size_t)DD * DD];

__device__ float g_sa[NC * BB * DD];
__device__ float g_sb[NC * BB * DD];
__device__ float g_ain[NC * BB * DD];
__device__ float g_bin[NC * BB * DD];

// ---------------------------------------------------------------------------
// PTX helpers (arch-portable: cp.async / ldmatrix / mma.sync)
// ---------------------------------------------------------------------------
__device__ __forceinline__ uint32_t smem_u32(const void* p) {
    uint32_t a;
    asm("{ .reg .u64 t; cvta.to.shared.u64 t, %1; cvt.u32.u64 %0, t; }"
        : "=r"(a) : "l"(p));
    return a;
}

__device__ __forceinline__ void cp16(uint32_t dst, const void* src) {
    asm volatile("cp.async.cg.shared.global [%0], [%1], 16;"
                 :: "r"(dst), "l"(src) : "memory");
}

__device__ __forceinline__ void cp_commit() {
    asm volatile("cp.async.commit_group;" ::: "memory");
}

template <int N>
__device__ __forceinline__ void cp_wait() {
    asm volatile("cp.async.wait_group %0;" :: "n"(N) : "memory");
}

__device__ __forceinline__ void ldsm4(uint32_t* r, uint32_t addr) {
    asm volatile("ldmatrix.sync.aligned.m8n8.x4.shared.b16 {%0,%1,%2,%3}, [%4];"
                 : "=r"(r[0]), "=r"(r[1]), "=r"(r[2]), "=r"(r[3]) : "r"(addr));
}

__device__ __forceinline__ void mma_f16(float* d, const uint32_t* a, const uint32_t* b) {
    asm volatile(
        "mma.sync.aligned.m16n8k16.row.col.f32.f16.f16.f32 "
        "{%0,%1,%2,%3}, {%4,%5,%6,%7}, {%8,%9}, {%0,%1,%2,%3};"
        : "+f"(d[0]), "+f"(d[1]), "+f"(d[2]), "+f"(d[3])
        : "r"(a[0]), "r"(a[1]), "r"(a[2]), "r"(a[3]), "r"(b[0]), "r"(b[1]));
}

// Swizzled smem offset for a [128 x 32] fp16 tile (rows of 4 x 16B chunks).
// 128B lines hold two rows; 8 chunk-positions per line XORed with line&7.
// Conflict-free for ldmatrix (8 consecutive rows, fixed chunk col).
__device__ __forceinline__ uint32_t phys(int r, int c) {
    return (uint32_t)((r >> 1) * 128 + ((((r & 1) * 4 + c) ^ ((r >> 1) & 7)) * 16));
}

// ---------------------------------------------------------------------------
// fp16 GEMM body via mma.sync:  C[m][n] = sum_k A[m][k]*W[n][k]
// Pure fp16 operands (1 pass). CTA tile 128x128, BK=32, 256 threads
// (8 warps, 2M x 4N). 6-stage ring, 16KB/stage -> 96KB -> 2 CTA/SM.
// Pass-major MMA order: same-acc RAW distance = 16 MMAs.
// ---------------------------------------------------------------------------
constexpr int TILE_BYTES = 128 * 32 * 2;           // 8192
constexpr int PIPE = 6;
constexpr int NSTAGE = DD / 32;                    // 32
constexpr int SBYTES = 2 * TILE_BYTES;             // 16384
constexpr int GEMM_SMEM = PIPE * SBYTES;           // 98304

template <bool SIG>
__device__ __forceinline__ void gemm_body(
    const __half* __restrict__ Ah, const __half* __restrict__ Wh,
    float* __restrict__ C, char* smem)
{
    constexpr int OFF_AH = 0;
    constexpr int OFF_WH = TILE_BYTES;

    const uint32_t sb = smem_u32(smem);
    const int tid = threadIdx.x;
    const int wid = tid >> 5;
    const int l   = tid & 31;
    const int wm  = wid & 1;          // 0..1 (M)
    const int wn  = wid >> 1;         // 0..3 (N)
    const int bm  = blockIdx.y * 128;
    const int bn  = blockIdx.x * 128;

    // ---- loader mapping: each thread copies 2 x 16B chunks per tile ----
    const int lr = tid >> 1;                   // 0..127
    const int lc0 = (tid & 1) * 2;             // chunk 0 or 2
    const size_t arow = (size_t)(bm + lr) * DD;
    const size_t wrow = (size_t)(bn + lr) * DD;
    const uint32_t sw0 = phys(lr, lc0);
    const uint32_t sw1 = phys(lr, lc0 + 1);

    float acc[4][4][4];
#pragma unroll
    for (int i = 0; i < 4; i++)
#pragma unroll
        for (int j = 0; j < 4; j++)
#pragma unroll
            for (int e = 0; e < 4; e++) acc[i][j][e] = 0.0f;

    auto load_stage = [&](int buf, int kc) {
        const uint32_t base = sb + buf * SBYTES;
        const __half* pa_h = Ah + arow + kc + lc0 * 8;
        const __half* pw_h = Wh + wrow + kc + lc0 * 8;
        cp16(base + OFF_AH + sw0, pa_h);
        cp16(base + OFF_AH + sw1, pa_h + 8);
        cp16(base + OFF_WH + sw0, pw_h);
        cp16(base + OFF_WH + sw1, pw_h + 8);
    };

    // ---- ldmatrix lane-address components ----
    const int ra = wm * 64 + (l & 7) + ((l >> 3) & 1) * 8;   // + mt*16
    const int ca = (l >> 4) & 1;                              // + ks*2
    const int rb = wn * 32 + (l & 7) + ((l >> 4) & 1) * 8;   // + nt2*16
    const int cb = (l >> 3) & 1;                              // + ks*2

    // ---- preload PIPE-1 stages ----
#pragma unroll
    for (int i = 0; i < PIPE - 1; i++) {
        load_stage(i, i * 32);
        cp_commit();
    }

    int buf = 0;
    for (int s = 0; s < NSTAGE; s++) {
        cp_wait<PIPE - 2>();
        __syncthreads();

        if (s + PIPE - 1 < NSTAGE)
            load_stage((s + PIPE - 1) % PIPE, (s + PIPE - 1) * 32);
        cp_commit();

        const uint32_t base = sb + buf * SBYTES;
#pragma unroll
        for (int ks = 0; ks < 2; ks++) {
            uint32_t fa[16], fb[8];
#pragma unroll
            for (int mt = 0; mt < 4; mt++) {
                const uint32_t off = phys(ra + mt * 16, ks * 2 + ca);
                ldsm4(fa + mt * 4, base + OFF_AH + off);
            }
#pragma unroll
            for (int nt2 = 0; nt2 < 2; nt2++) {
                const uint32_t off = phys(rb + nt2 * 16, ks * 2 + cb);
                ldsm4(fb + nt2 * 4, base + OFF_WH + off);
            }
#pragma unroll
            for (int mt = 0; mt < 4; mt++)
#pragma unroll
                for (int nt = 0; nt < 4; nt++)
                    mma_f16(acc[mt][nt], fa + mt * 4, fb + nt * 2);
        }
        buf = (buf + 1 == PIPE) ? 0 : buf + 1;
    }

    // ---- epilogue ----
    const int er = l >> 2;            // 0..7
    const int ec = (l & 3) * 2;       // 0,2,4,6
#pragma unroll
    for (int mt = 0; mt < 4; mt++) {
#pragma unroll
        for (int nt = 0; nt < 4; nt++) {
            const int m0 = bm + wm * 64 + mt * 16 + er;
            const int n0 = bn + wn * 32 + nt * 8 + ec;
            float v0 = acc[mt][nt][0], v1 = acc[mt][nt][1];
            float v2 = acc[mt][nt][2], v3 = acc[mt][nt][3];
            if (SIG) {
                v0 = 1.0f / (1.0f + __expf(-v0));
                v1 = 1.0f / (1.0f + __expf(-v1));
                v2 = 1.0f / (1.0f + __expf(-v2));
                v3 = 1.0f / (1.0f + __expf(-v3));
            }
            *(float2*)(C + (size_t)m0 * DD + n0)       = make_float2(v0, v1);
            *(float2*)(C + (size_t)(m0 + 8) * DD + n0) = make_float2(v2, v3);
        }
    }
}

// Fused k/v/r projection launch: blockIdx.z selects the GEMM.
__global__ void __launch_bounds__(256, 2)
gemm_kvr(const __half* __restrict__ xkh, const __half* __restrict__ xvh,
         const __half* __restrict__ xrh,
         const __half* __restrict__ whk, const __half* __restrict__ whv,
         const __half* __restrict__ whr,
         float* __restrict__ gk, float* __restrict__ gv, float* __restrict__ gr)
{
    extern __shared__ char smem[];
    if (blockIdx.z == 0)
        gemm_body<false>(xkh, whk, gk, smem);
    else if (blockIdx.z == 1)
        gemm_body<false>(xvh, whv, gv, smem);
    else
        gemm_body<true>(xrh, whr, gr, smem);
}

// Output projection
__global__ void __launch_bounds__(256, 2)
gemm_o(const __half* __restrict__ Ah, const __half* __restrict__ Wh,
       float* __restrict__ C)
{
    extern __shared__ char smem[];
    gemm_body<false>(Ah, Wh, C, smem);
}

// ---------------------------------------------------------------------------
// Conversion: token-shift mix -> fp16 (hi only) for all three projections
// ---------------------------------------------------------------------------
__global__ void conv_x(const float* __restrict__ x,
                       const float* __restrict__ mk, const float* __restrict__ mv,
                       const float* __restrict__ mr,
                       __half* __restrict__ kh, __half* __restrict__ vh,
                       __half* __restrict__ rh)
{
    const size_t gid = (size_t)blockIdx.x * blockDim.x + threadIdx.x;
    const size_t idx = gid * 4;
    const int d = (int)(idx % DD);
    const size_t m = idx / DD;
    const int lpos = (int)(m & (LL - 1));

    const float4 xc = *(const float4*)(x + idx);
    float4 xp = make_float4(0.f, 0.f, 0.f, 0.f);
    if (lpos != 0) xp = *(const float4*)(x + idx - DD);

    const float xcv[4] = {xc.x, xc.y, xc.z, xc.w};
    const float xpv[4] = {xp.x, xp.y, xp.z, xp.w};

    const float* mixes[3] = {mk, mv, mr};
    __half* outh[3] = {kh, vh, rh};

#pragma unroll
    for (int s = 0; s < 3; s++) {
        const float4 mx = *(const float4*)(mixes[s] + d);
        const float mxv[4] = {mx.x, mx.y, mx.z, mx.w};
        unsigned short hh[4];
#pragma unroll
        for (int j = 0; j < 4; j++) {
            const float a = xcv[j] * mxv[j] + xpv[j] * (1.0f - mxv[j]);
            hh[j] = __half_as_ushort(__float2half_rn(a));
        }
        *(ushort4*)(outh[s] + idx) = make_ushort4(hh[0], hh[1], hh[2], hh[3]);
    }
}

// All 4 weight matrices -> fp16 (hi only)
__global__ void conv_w_all(const float* __restrict__ W0, const float* __restrict__ W1,
                           const float* __restrict__ W2, const float* __restrict__ W3,
                           __half* __restrict__ WH)
{
    constexpr size_t WS = (size_t)DD * DD;
    const size_t gid = (size_t)blockIdx.x * blockDim.x + threadIdx.x;
    const size_t idx = gid * 4;                 // over 4*WS elements
    const int mat = (int)(idx / WS);
    const size_t off = idx % WS;
    const float* W = (mat == 0) ? W0 : (mat == 1) ? W1 : (mat == 2) ? W2 : W3;

    const float4 w4 = *(const float4*)(W + off);
    unsigned short hh[4];
    hh[0] = __half_as_ushort(__float2half_rn(w4.x));
    hh[1] = __half_as_ushort(__float2half_rn(w4.y));
    hh[2] = __half_as_ushort(__float2half_rn(w4.z));
    hh[3] = __half_as_ushort(__float2half_rn(w4.w));
    *(ushort4*)(WH + idx) = make_ushort4(hh[0], hh[1], hh[2], hh[3]);
}

// ---------------------------------------------------------------------------
// WKV scan (chunk-parallel affine recurrence), NC=64 chunks
// ---------------------------------------------------------------------------
__global__ void wkv_phase1(const float* __restrict__ K_,
                           const float* __restrict__ V_,
                           const float* __restrict__ td,
                           float* __restrict__ SA,
                           float* __restrict__ SB)
{
    const int gid = blockIdx.x * blockDim.x + threadIdx.x;
    const int d = gid % DD;
    const int b = (gid / DD) % BB;
    const int c = gid / (DD * BB);

    const float w = -expf(td[d]);
    const float decay = expf(w);

    size_t base = ((size_t)(b * LL + c * CL)) * DD + d;
    float sa = 0.0f, sb = 0.0f;
#pragma unroll 4
    for (int t = 0; t < CL; t++) {
        const float kt = K_[base];
        const float vt = V_[base];
        const float ek = expf(kt);
        sa = decay * sa + ek * vt;
        sb = decay * sb + ek;
        base += DD;
    }
    SA[gid] = sa;
    SB[gid] = sb;
}

__global__ void wkv_phase2(const float* __restrict__ SA,
                           const float* __restrict__ SB,
                           const float* __restrict__ td,
                           float* __restrict__ AIN,
                           float* __restrict__ BIN)
{
    const int gid = blockIdx.x * blockDim.x + threadIdx.x;
    const int d = gid % DD;
    const int b = gid / DD;

    const float w = -expf(td[d]);
    const float dpow = expf(w * (float)CL);

    float a = 0.0f, bs = 0.0f;
#pragma unroll
    for (int c = 0; c < NC; c++) {
        const size_t sidx = ((size_t)c * BB + b) * DD + d;
        AIN[sidx] = a;
        BIN[sidx] = bs;
        a  = dpow * a  + SA[sidx];
        bs = dpow * bs + SB[sidx];
    }
}

__global__ void wkv_phase3(const float* __restrict__ K_,
                           const float* __restrict__ V_,
                           const float* __restrict__ td,
                           const float* __restrict__ tf,
                           const float* __restrict__ AIN,
                           const float* __restrict__ BIN,
                           const float* __restrict__ R,
                           __half* __restrict__ RWH)
{
    const int gid = blockIdx.x * blockDim.x + threadIdx.x;
    const int d = gid % DD;
    const int b = (gid / DD) % BB;
    const int c = gid / (DD * BB);

    const float w = -expf(td[d]);
    const float decay = expf(w);
    const float u = tf[d];

    float a  = AIN[gid];
    float bs = BIN[gid];

    size_t base = ((size_t)(b * LL + c * CL)) * DD + d;
#pragma unroll 4
    for (int t = 0; t < CL; t++) {
        const float kt = K_[base];
        const float vt = V_[base];
        const float eku = expf(u + kt);
        const float wkv = (a + eku * vt) / fmaxf(bs + eku, 1e-6f);
        const float ek = expf(kt);
        RWH[base] = __float2half_rn(R[base] * wkv);
        a  = decay * a  + ek * vt;
        bs = decay * bs + ek;
        base += DD;
    }
}

// ---------------------------------------------------------------------------
extern "C" void kernel_launch(void* const* d_in, const int* in_sizes, int n_in,
                              void* d_out, int out_size)
{
    const float* x  = (const float*)d_in[0];
    const float* td = (const float*)d_in[1];
    const float* tf = (const float*)d_in[2];
    const float* mk = (const float*)d_in[3];
    const float* mv = (const float*)d_in[4];
    const float* mr = (const float*)d_in[5];
    const float* Wk = (const float*)d_in[6];
    const float* Wv = (const float*)d_in[7];
    const float* Wr = (const float*)d_in[8];
    const float* Wo = (const float*)d_in[9];
    float* out = (float*)d_out;

    float *gk, *gv, *gr, *gsa, *gsb, *gain, *gbin;
    __half *xkh, *xvh, *xrh, *rwh, *wh;
    cudaGetSymbolAddress((void**)&gk,   g_k);
    cudaGetSymbolAddress((void**)&gv,   g_v);
    cudaGetSymbolAddress((void**)&gr,   g_r);
    cudaGetSymbolAddress((void**)&gsa,  g_sa);
    cudaGetSymbolAddress((void**)&gsb,  g_sb);
    cudaGetSymbolAddress((void**)&gain, g_ain);
    cudaGetSymbolAddress((void**)&gbin, g_bin);
    cudaGetSymbolAddress((void**)&xkh,  g_xkh);
    cudaGetSymbolAddress((void**)&xvh,  g_xvh);
    cudaGetSymbolAddress((void**)&xrh,  g_xrh);
    cudaGetSymbolAddress((void**)&rwh,  g_rwh);
    cudaGetSymbolAddress((void**)&wh,   g_wh);

    cudaFuncSetAttribute(gemm_kvr,
                         cudaFuncAttributeMaxDynamicSharedMemorySize, GEMM_SMEM);
    cudaFuncSetAttribute(gemm_o,
                         cudaFuncAttributeMaxDynamicSharedMemorySize, GEMM_SMEM);

    const size_t WSTRIDE = (size_t)DD * DD;

    // launch 0: conv_x, 1: conv_w_all
    conv_x<<<(int)(((size_t)MM * DD / 4) / 256), 256>>>(x, mk, mv, mr,
                                                        xkh, xvh, xrh);
    conv_w_all<<<(int)((4 * WSTRIDE / 4) / 256), 256>>>(Wk, Wv, Wr, Wo, wh);

    // launch 2: fused k/v/r projections (3072 CTAs, uniform 1-pass bodies)
    const dim3 ggz(DD / 128, MM / 128, 3);
    gemm_kvr<<<ggz, 256, GEMM_SMEM>>>(xkh, xvh, xrh,
                                      wh + 0 * WSTRIDE, wh + 1 * WSTRIDE,
                                      wh + 2 * WSTRIDE,
                                      gk, gv, gr);

    // launches 3-5: wkv scan
    wkv_phase1<<<(NC * BB * DD) / 256, 256>>>(gk, gv, td, gsa, gsb);
    wkv_phase2<<<(BB * DD) / 256, 256>>>(gsa, gsb, td, gain, gbin);
    wkv_phase3<<<(NC * BB * DD) / 256, 256>>>(gk, gv, td, tf, gain, gbin, gr, rwh);

    // launch 6: output projection
    const dim3 gg(DD / 128, MM / 128);
    gemm_o<<<gg, 256, GEMM_SMEM>>>(rwh, wh + 3 * WSTRIDE, out);
}

// round 17
// speedup vs baseline: 2.2218x; 1.0457x over previous
#include <cuda_runtime.h>
#include <cuda_fp16.h>
#include <math.h>
#include <cstdint>
#include <cstddef>

// Problem constants
constexpr int BB = 4;
constexpr int LL = 4096;
constexpr int DD = 1024;
constexpr int MM = BB * LL;           // 16384 rows
constexpr int NC = 64;                // scan chunks
constexpr int CL = LL / NC;           // 64 steps per chunk

// ---------------------------------------------------------------------------
// Static device scratch (no allocations allowed)
// ---------------------------------------------------------------------------
__device__ __half g_k[(size_t)MM * DD];
__device__ __half g_v[(size_t)MM * DD];
__device__ __half g_r[(size_t)MM * DD];

__device__ __half g_xkh[(size_t)MM * DD];
__device__ __half g_xvh[(size_t)MM * DD];
__device__ __half g_xrh[(size_t)MM * DD];
__device__ __half g_rwh[(size_t)MM * DD];

__device__ __half g_wh[4][(size_t)DD * DD];

__device__ float g_sa[NC * BB * DD];
__device__ float g_sb[NC * BB * DD];
__device__ float g_ain[NC * BB * DD];
__device__ float g_bin[NC * BB * DD];

// ---------------------------------------------------------------------------
// PTX helpers (arch-portable: cp.async / ldmatrix / mma.sync)
// ---------------------------------------------------------------------------
__device__ __forceinline__ uint32_t smem_u32(const void* p) {
    uint32_t a;
    asm("{ .reg .u64 t; cvta.to.shared.u64 t, %1; cvt.u32.u64 %0, t; }"
        : "=r"(a) : "l"(p));
    return a;
}

__device__ __forceinline__ void cp16(uint32_t dst, const void* src) {
    asm volatile("cp.async.cg.shared.global [%0], [%1], 16;"
                 :: "r"(dst), "l"(src) : "memory");
}

__device__ __forceinline__ void cp_commit() {
    asm volatile("cp.async.commit_group;" ::: "memory");
}

template <int N>
__device__ __forceinline__ void cp_wait() {
    asm volatile("cp.async.wait_group %0;" :: "n"(N) : "memory");
}

__device__ __forceinline__ void ldsm4(uint32_t* r, uint32_t addr) {
    asm volatile("ldmatrix.sync.aligned.m8n8.x4.shared.b16 {%0,%1,%2,%3}, [%4];"
                 : "=r"(r[0]), "=r"(r[1]), "=r"(r[2]), "=r"(r[3]) : "r"(addr));
}

__device__ __forceinline__ void mma_f16(float* d, const uint32_t* a, const uint32_t* b) {
    asm volatile(
        "mma.sync.aligned.m16n8k16.row.col.f32.f16.f16.f32 "
        "{%0,%1,%2,%3}, {%4,%5,%6,%7}, {%8,%9}, {%0,%1,%2,%3};"
        : "+f"(d[0]), "+f"(d[1]), "+f"(d[2]), "+f"(d[3])
        : "r"(a[0]), "r"(a[1]), "r"(a[2]), "r"(a[3]), "r"(b[0]), "r"(b[1]));
}

// Swizzled smem offset for a [128 x 32] fp16 tile (rows of 4 x 16B chunks).
// 128B lines hold two rows; 8 chunk-positions per line XORed with line&7.
// Conflict-free for ldmatrix (8 consecutive rows, fixed chunk col).
__device__ __forceinline__ uint32_t phys(int r, int c) {
    return (uint32_t)((r >> 1) * 128 + ((((r & 1) * 4 + c) ^ ((r >> 1) & 7)) * 16));
}

// ---------------------------------------------------------------------------
// fp16 GEMM body via mma.sync:  C[m][n] = sum_k A[m][k]*W[n][k]
// Pure fp16 operands (1 pass). CTA tile 128x128, BK=32, 256 threads
// (8 warps, 2M x 4N). 6-stage ring, 16KB/stage -> 96KB -> 2 CTA/SM.
// HALF_OUT: write __half (k/v/r intermediates); else fp32 (final output).
// ---------------------------------------------------------------------------
constexpr int TILE_BYTES = 128 * 32 * 2;           // 8192
constexpr int PIPE = 6;
constexpr int NSTAGE = DD / 32;                    // 32
constexpr int SBYTES = 2 * TILE_BYTES;             // 16384
constexpr int GEMM_SMEM = PIPE * SBYTES;           // 98304

template <bool SIG, bool HALF_OUT>
__device__ __forceinline__ void gemm_body(
    const __half* __restrict__ Ah, const __half* __restrict__ Wh,
    void* __restrict__ Cv, char* smem)
{
    constexpr int OFF_AH = 0;
    constexpr int OFF_WH = TILE_BYTES;

    const uint32_t sb = smem_u32(smem);
    const int tid = threadIdx.x;
    const int wid = tid >> 5;
    const int l   = tid & 31;
    const int wm  = wid & 1;          // 0..1 (M)
    const int wn  = wid >> 1;         // 0..3 (N)
    const int bm  = blockIdx.y * 128;
    const int bn  = blockIdx.x * 128;

    // ---- loader mapping: each thread copies 2 x 16B chunks per tile ----
    const int lr = tid >> 1;                   // 0..127
    const int lc0 = (tid & 1) * 2;             // chunk 0 or 2
    const size_t arow = (size_t)(bm + lr) * DD;
    const size_t wrow = (size_t)(bn + lr) * DD;
    const uint32_t sw0 = phys(lr, lc0);
    const uint32_t sw1 = phys(lr, lc0 + 1);

    float acc[4][4][4];
#pragma unroll
    for (int i = 0; i < 4; i++)
#pragma unroll
        for (int j = 0; j < 4; j++)
#pragma unroll
            for (int e = 0; e < 4; e++) acc[i][j][e] = 0.0f;

    auto load_stage = [&](int buf, int kc) {
        const uint32_t base = sb + buf * SBYTES;
        const __half* pa_h = Ah + arow + kc + lc0 * 8;
        const __half* pw_h = Wh + wrow + kc + lc0 * 8;
        cp16(base + OFF_AH + sw0, pa_h);
        cp16(base + OFF_AH + sw1, pa_h + 8);
        cp16(base + OFF_WH + sw0, pw_h);
        cp16(base + OFF_WH + sw1, pw_h + 8);
    };

    // ---- ldmatrix lane-address components ----
    const int ra = wm * 64 + (l & 7) + ((l >> 3) & 1) * 8;   // + mt*16
    const int ca = (l >> 4) & 1;                              // + ks*2
    const int rb = wn * 32 + (l & 7) + ((l >> 4) & 1) * 8;   // + nt2*16
    const int cb = (l >> 3) & 1;                              // + ks*2

    // ---- preload PIPE-1 stages ----
#pragma unroll
    for (int i = 0; i < PIPE - 1; i++) {
        load_stage(i, i * 32);
        cp_commit();
    }

    int buf = 0;
    for (int s = 0; s < NSTAGE; s++) {
        cp_wait<PIPE - 2>();
        __syncthreads();

        if (s + PIPE - 1 < NSTAGE)
            load_stage((s + PIPE - 1) % PIPE, (s + PIPE - 1) * 32);
        cp_commit();

        const uint32_t base = sb + buf * SBYTES;
#pragma unroll
        for (int ks = 0; ks < 2; ks++) {
            uint32_t fa[16], fb[8];
#pragma unroll
            for (int mt = 0; mt < 4; mt++) {
                const uint32_t off = phys(ra + mt * 16, ks * 2 + ca);
                ldsm4(fa + mt * 4, base + OFF_AH + off);
            }
#pragma unroll
            for (int nt2 = 0; nt2 < 2; nt2++) {
                const uint32_t off = phys(rb + nt2 * 16, ks * 2 + cb);
                ldsm4(fb + nt2 * 4, base + OFF_WH + off);
            }
#pragma unroll
            for (int mt = 0; mt < 4; mt++)
#pragma unroll
                for (int nt = 0; nt < 4; nt++)
                    mma_f16(acc[mt][nt], fa + mt * 4, fb + nt * 2);
        }
        buf = (buf + 1 == PIPE) ? 0 : buf + 1;
    }

    // ---- epilogue ----
    const int er = l >> 2;            // 0..7
    const int ec = (l & 3) * 2;       // 0,2,4,6
#pragma unroll
    for (int mt = 0; mt < 4; mt++) {
#pragma unroll
        for (int nt = 0; nt < 4; nt++) {
            const int m0 = bm + wm * 64 + mt * 16 + er;
            const int n0 = bn + wn * 32 + nt * 8 + ec;
            float v0 = acc[mt][nt][0], v1 = acc[mt][nt][1];
            float v2 = acc[mt][nt][2], v3 = acc[mt][nt][3];
            if (SIG) {
                v0 = 1.0f / (1.0f + __expf(-v0));
                v1 = 1.0f / (1.0f + __expf(-v1));
                v2 = 1.0f / (1.0f + __expf(-v2));
                v3 = 1.0f / (1.0f + __expf(-v3));
            }
            if (HALF_OUT) {
                __half* C = (__half*)Cv;
                *(__half2*)(C + (size_t)m0 * DD + n0)       = __floats2half2_rn(v0, v1);
                *(__half2*)(C + (size_t)(m0 + 8) * DD + n0) = __floats2half2_rn(v2, v3);
            } else {
                float* C = (float*)Cv;
                *(float2*)(C + (size_t)m0 * DD + n0)       = make_float2(v0, v1);
                *(float2*)(C + (size_t)(m0 + 8) * DD + n0) = make_float2(v2, v3);
            }
        }
    }
}

// Fused k/v/r projection launch: blockIdx.z selects the GEMM. Half outputs.
__global__ void __launch_bounds__(256, 2)
gemm_kvr(const __half* __restrict__ xkh, const __half* __restrict__ xvh,
         const __half* __restrict__ xrh,
         const __half* __restrict__ whk, const __half* __restrict__ whv,
         const __half* __restrict__ whr,
         __half* __restrict__ gk, __half* __restrict__ gv, __half* __restrict__ gr)
{
    extern __shared__ char smem[];
    if (blockIdx.z == 0)
        gemm_body<false, true>(xkh, whk, gk, smem);
    else if (blockIdx.z == 1)
        gemm_body<false, true>(xvh, whv, gv, smem);
    else
        gemm_body<true, true>(xrh, whr, gr, smem);
}

// Output projection (fp32 output)
__global__ void __launch_bounds__(256, 2)
gemm_o(const __half* __restrict__ Ah, const __half* __restrict__ Wh,
       float* __restrict__ C)
{
    extern __shared__ char smem[];
    gemm_body<false, false>(Ah, Wh, C, smem);
}

// ---------------------------------------------------------------------------
// Conversion: token-shift mix -> fp16 for all three projections
// ---------------------------------------------------------------------------
__global__ void conv_x(const float* __restrict__ x,
                       const float* __restrict__ mk, const float* __restrict__ mv,
                       const float* __restrict__ mr,
                       __half* __restrict__ kh, __half* __restrict__ vh,
                       __half* __restrict__ rh)
{
    const size_t gid = (size_t)blockIdx.x * blockDim.x + threadIdx.x;
    const size_t idx = gid * 4;
    const int d = (int)(idx % DD);
    const size_t m = idx / DD;
    const int lpos = (int)(m & (LL - 1));

    const float4 xc = *(const float4*)(x + idx);
    float4 xp = make_float4(0.f, 0.f, 0.f, 0.f);
    if (lpos != 0) xp = *(const float4*)(x + idx - DD);

    const float xcv[4] = {xc.x, xc.y, xc.z, xc.w};
    const float xpv[4] = {xp.x, xp.y, xp.z, xp.w};

    const float* mixes[3] = {mk, mv, mr};
    __half* outh[3] = {kh, vh, rh};

#pragma unroll
    for (int s = 0; s < 3; s++) {
        const float4 mx = *(const float4*)(mixes[s] + d);
        const float mxv[4] = {mx.x, mx.y, mx.z, mx.w};
        unsigned short hh[4];
#pragma unroll
        for (int j = 0; j < 4; j++) {
            const float a = xcv[j] * mxv[j] + xpv[j] * (1.0f - mxv[j]);
            hh[j] = __half_as_ushort(__float2half_rn(a));
        }
        *(ushort4*)(outh[s] + idx) = make_ushort4(hh[0], hh[1], hh[2], hh[3]);
    }
}

// All 4 weight matrices -> fp16
__global__ void conv_w_all(const float* __restrict__ W0, const float* __restrict__ W1,
                           const float* __restrict__ W2, const float* __restrict__ W3,
                           __half* __restrict__ WH)
{
    constexpr size_t WS = (size_t)DD * DD;
    const size_t gid = (size_t)blockIdx.x * blockDim.x + threadIdx.x;
    const size_t idx = gid * 4;                 // over 4*WS elements
    const int mat = (int)(idx / WS);
    const size_t off = idx % WS;
    const float* W = (mat == 0) ? W0 : (mat == 1) ? W1 : (mat == 2) ? W2 : W3;

    const float4 w4 = *(const float4*)(W + off);
    unsigned short hh[4];
    hh[0] = __half_as_ushort(__float2half_rn(w4.x));
    hh[1] = __half_as_ushort(__float2half_rn(w4.y));
    hh[2] = __half_as_ushort(__float2half_rn(w4.z));
    hh[3] = __half_as_ushort(__float2half_rn(w4.w));
    *(ushort4*)(WH + idx) = make_ushort4(hh[0], hh[1], hh[2], hh[3]);
}

// ---------------------------------------------------------------------------
// WKV scan (chunk-parallel affine recurrence), NC=64 chunks.
// fp16 k/v/r inputs; 2 channels per thread via __half2 (128B/warp coalesced).
// fp32 state and per-channel decay (computed once with accurate expf).
// ---------------------------------------------------------------------------
__global__ void wkv_phase1(const __half2* __restrict__ K2,
                           const __half2* __restrict__ V2,
                           const float* __restrict__ td,
                           float* __restrict__ SA,
                           float* __restrict__ SB)
{
    constexpr int HD = DD / 2;
    const int gid = blockIdx.x * blockDim.x + threadIdx.x;   // NC*BB*HD threads
    const int d2 = gid % HD;
    const int b = (gid / HD) % BB;
    const int c = gid / (HD * BB);

    const float2 tdv = *(const float2*)(td + 2 * d2);
    const float dec0 = expf(-expf(tdv.x));
    const float dec1 = expf(-expf(tdv.y));

    size_t base = ((size_t)(b * LL + c * CL)) * HD + d2;
    float sa0 = 0.f, sb0 = 0.f, sa1 = 0.f, sb1 = 0.f;
#pragma unroll 4
    for (int t = 0; t < CL; t++) {
        const float2 kf = __half22float2(K2[base]);
        const float2 vf = __half22float2(V2[base]);
        const float ek0 = __expf(kf.x);
        const float ek1 = __expf(kf.y);
        sa0 = dec0 * sa0 + ek0 * vf.x;
        sb0 = dec0 * sb0 + ek0;
        sa1 = dec1 * sa1 + ek1 * vf.y;
        sb1 = dec1 * sb1 + ek1;
        base += HD;
    }
    const size_t sidx = ((size_t)(c * BB + b)) * DD + 2 * d2;
    *(float2*)(SA + sidx) = make_float2(sa0, sa1);
    *(float2*)(SB + sidx) = make_float2(sb0, sb1);
}

__global__ void wkv_phase2(const float* __restrict__ SA,
                           const float* __restrict__ SB,
                           const float* __restrict__ td,
                           float* __restrict__ AIN,
                           float* __restrict__ BIN)
{
    const int gid = blockIdx.x * blockDim.x + threadIdx.x;   // BB*DD threads
    const int d = gid % DD;
    const int b = gid / DD;

    const float w = -expf(td[d]);
    const float dpow = expf(w * (float)CL);

    float a = 0.0f, bs = 0.0f;
#pragma unroll
    for (int c = 0; c < NC; c++) {
        const size_t sidx = ((size_t)c * BB + b) * DD + d;
        AIN[sidx] = a;
        BIN[sidx] = bs;
        a  = dpow * a  + SA[sidx];
        bs = dpow * bs + SB[sidx];
    }
}

__global__ void wkv_phase3(const __half2* __restrict__ K2,
                           const __half2* __restrict__ V2,
                           const float* __restrict__ td,
                           const float* __restrict__ tf,
                           const float* __restrict__ AIN,
                           const float* __restrict__ BIN,
                           const __half2* __restrict__ R2,
                           __half2* __restrict__ RWH)
{
    constexpr int HD = DD / 2;
    const int gid = blockIdx.x * blockDim.x + threadIdx.x;   // NC*BB*HD threads
    const int d2 = gid % HD;
    const int b = (gid / HD) % BB;
    const int c = gid / (HD * BB);

    const float2 tdv = *(const float2*)(td + 2 * d2);
    const float dec0 = expf(-expf(tdv.x));
    const float dec1 = expf(-expf(tdv.y));
    const float2 uv = *(const float2*)(tf + 2 * d2);

    const size_t sidx = ((size_t)(c * BB + b)) * DD + 2 * d2;
    const float2 a0v = *(const float2*)(AIN + sidx);
    const float2 b0v = *(const float2*)(BIN + sidx);
    float a0 = a0v.x, a1 = a0v.y;
    float bs0 = b0v.x, bs1 = b0v.y;

    size_t base = ((size_t)(b * LL + c * CL)) * HD + d2;
#pragma unroll 4
    for (int t = 0; t < CL; t++) {
        const float2 kf = __half22float2(K2[base]);
        const float2 vf = __half22float2(V2[base]);
        const float2 rf = __half22float2(R2[base]);
        const float eku0 = __expf(uv.x + kf.x);
        const float eku1 = __expf(uv.y + kf.y);
        const float wkv0 = (a0 + eku0 * vf.x) / fmaxf(bs0 + eku0, 1e-6f);
        const float wkv1 = (a1 + eku1 * vf.y) / fmaxf(bs1 + eku1, 1e-6f);
        const float ek0 = __expf(kf.x);
        const float ek1 = __expf(kf.y);
        RWH[base] = __floats2half2_rn(rf.x * wkv0, rf.y * wkv1);
        a0  = dec0 * a0  + ek0 * vf.x;
        bs0 = dec0 * bs0 + ek0;
        a1  = dec1 * a1  + ek1 * vf.y;
        bs1 = dec1 * bs1 + ek1;
        base += HD;
    }
}

// ---------------------------------------------------------------------------
extern "C" void kernel_launch(void* const* d_in, const int* in_sizes, int n_in,
                              void* d_out, int out_size)
{
    const float* x  = (const float*)d_in[0];
    const float* td = (const float*)d_in[1];
    const float* tf = (const float*)d_in[2];
    const float* mk = (const float*)d_in[3];
    const float* mv = (const float*)d_in[4];
    const float* mr = (const float*)d_in[5];
    const float* Wk = (const float*)d_in[6];
    const float* Wv = (const float*)d_in[7];
    const float* Wr = (const float*)d_in[8];
    const float* Wo = (const float*)d_in[9];
    float* out = (float*)d_out;

    __half *gk, *gv, *gr, *xkh, *xvh, *xrh, *rwh, *wh;
    float *gsa, *gsb, *gain, *gbin;
    cudaGetSymbolAddress((void**)&gk,   g_k);
    cudaGetSymbolAddress((void**)&gv,   g_v);
    cudaGetSymbolAddress((void**)&gr,   g_r);
    cudaGetSymbolAddress((void**)&gsa,  g_sa);
    cudaGetSymbolAddress((void**)&gsb,  g_sb);
    cudaGetSymbolAddress((void**)&gain, g_ain);
    cudaGetSymbolAddress((void**)&gbin, g_bin);
    cudaGetSymbolAddress((void**)&xkh,  g_xkh);
    cudaGetSymbolAddress((void**)&xvh,  g_xvh);
    cudaGetSymbolAddress((void**)&xrh,  g_xrh);
    cudaGetSymbolAddress((void**)&rwh,  g_rwh);
    cudaGetSymbolAddress((void**)&wh,   g_wh);

    cudaFuncSetAttribute(gemm_kvr,
                         cudaFuncAttributeMaxDynamicSharedMemorySize, GEMM_SMEM);
    cudaFuncSetAttribute(gemm_o,
                         cudaFuncAttributeMaxDynamicSharedMemorySize, GEMM_SMEM);

    const size_t WSTRIDE = (size_t)DD * DD;

    // launch 0: conv_x, 1: conv_w_all
    conv_x<<<(int)(((size_t)MM * DD / 4) / 256), 256>>>(x, mk, mv, mr,
                                                        xkh, xvh, xrh);
    conv_w_all<<<(int)((4 * WSTRIDE / 4) / 256), 256>>>(Wk, Wv, Wr, Wo, wh);

    // launch 2: fused k/v/r projections (3072 CTAs, fp16 outputs)
    const dim3 ggz(DD / 128, MM / 128, 3);
    gemm_kvr<<<ggz, 256, GEMM_SMEM>>>(xkh, xvh, xrh,
                                      wh + 0 * WSTRIDE, wh + 1 * WSTRIDE,
                                      wh + 2 * WSTRIDE,
                                      gk, gv, gr);

    // launches 3-5: wkv scan (half2 I/O)
    wkv_phase1<<<(NC * BB * DD / 2) / 256, 256>>>((const __half2*)gk, (const __half2*)gv,
                                                  td, gsa, gsb);
    wkv_phase2<<<(BB * DD) / 256, 256>>>(gsa, gsb, td, gain, gbin);
    wkv_phase3<<<(NC * BB * DD / 2) / 256, 256>>>((const __half2*)gk, (const __half2*)gv,
                                                  td, tf, gain, gbin,
                                                  (const __half2*)gr, (__half2*)rwh);

    // launch 6: output projection
    const dim3 gg(DD / 128, MM / 128);
    gemm_o<<<gg, 256, GEMM_SMEM>>>(rwh, wh + 3 * WSTRIDE, out);
}